// round 3
// baseline (speedup 1.0000x reference)
#include <cuda_runtime.h>
#include <math_constants.h>

// Problem constants
#define BATCH 4
#define NSEQ  2048
#define CDIM  1024
#define HEADS 16
#define DH    64
#define MROWS (BATCH*NSEQ)                 // 8192
#define QKV_ELEMS (BATCH*HEADS*NSEQ*DH)    // 8388608

// Scratch (static device globals; allocation inside kernel_launch is forbidden)
__device__ float g_q[QKV_ELEMS];
__device__ float g_k[QKV_ELEMS];
__device__ float g_v[QKV_ELEMS];
__device__ float g_o[MROWS*CDIM];

// ---------------------------------------------------------------------------
// NT GEMM: C[m,n] = sum_k A[m,k] * B[n,k]
// 128x128 tile, BK=16, 256 threads, 8x8 micro-tile, register double buffering.
// EPI==0: plain write to C.
// EPI==1: scatter epilogue into g_q/g_k/g_v per qkv/head/dim decomposition.
// ---------------------------------------------------------------------------
template<int EPI>
__global__ __launch_bounds__(256, 2)
void gemm_nt_kernel(const float* __restrict__ A, const float* __restrict__ B,
                    float* __restrict__ C, int N, int K)
{
    __shared__ float As[16][132];   // [k][m], +4 pad keeps 16B alignment, spreads banks
    __shared__ float Bs[16][132];   // [k][n]

    const int tid = threadIdx.x;
    const int tr  = tid >> 4;       // 0..15  (m micro-row)
    const int tc  = tid & 15;       // 0..15  (n micro-col)
    const int m0  = blockIdx.y * 128;
    const int n0  = blockIdx.x * 128;

    // tile-load mapping: float4 id v in [0,512): row = v>>2, kquad = (v&3)*4
    const int lr = tid >> 2;              // 0..63
    const int lk = (tid & 3) * 4;         // 0,4,8,12
    const float* Ag = A + (size_t)(m0 + lr) * K + lk;
    const float* Bg = B + (size_t)(n0 + lr) * K + lk;
    const size_t rstep = (size_t)64 * K;

    float4 pa0 = *(const float4*)Ag;
    float4 pa1 = *(const float4*)(Ag + rstep);
    float4 pb0 = *(const float4*)Bg;
    float4 pb1 = *(const float4*)(Bg + rstep);

    float acc[8][8];
    #pragma unroll
    for (int i = 0; i < 8; ++i)
        #pragma unroll
        for (int j = 0; j < 8; ++j) acc[i][j] = 0.0f;

    const int T = K >> 4;
    for (int t = 0; t < T; ++t) {
        __syncthreads();
        As[lk+0][lr]    = pa0.x; As[lk+1][lr]    = pa0.y; As[lk+2][lr]    = pa0.z; As[lk+3][lr]    = pa0.w;
        As[lk+0][lr+64] = pa1.x; As[lk+1][lr+64] = pa1.y; As[lk+2][lr+64] = pa1.z; As[lk+3][lr+64] = pa1.w;
        Bs[lk+0][lr]    = pb0.x; Bs[lk+1][lr]    = pb0.y; Bs[lk+2][lr]    = pb0.z; Bs[lk+3][lr]    = pb0.w;
        Bs[lk+0][lr+64] = pb1.x; Bs[lk+1][lr+64] = pb1.y; Bs[lk+2][lr+64] = pb1.z; Bs[lk+3][lr+64] = pb1.w;
        __syncthreads();

        if (t + 1 < T) {   // prefetch next K-slab into registers (overlaps compute)
            const float* An = Ag + (size_t)(t + 1) * 16;
            const float* Bn = Bg + (size_t)(t + 1) * 16;
            pa0 = *(const float4*)An;
            pa1 = *(const float4*)(An + rstep);
            pb0 = *(const float4*)Bn;
            pb1 = *(const float4*)(Bn + rstep);
        }

        #pragma unroll
        for (int kk = 0; kk < 16; ++kk) {
            float4 a0 = *(const float4*)&As[kk][tr * 8];
            float4 a1 = *(const float4*)&As[kk][tr * 8 + 4];
            float4 b0 = *(const float4*)&Bs[kk][tc * 8];
            float4 b1 = *(const float4*)&Bs[kk][tc * 8 + 4];
            float av[8] = {a0.x, a0.y, a0.z, a0.w, a1.x, a1.y, a1.z, a1.w};
            float bv[8] = {b0.x, b0.y, b0.z, b0.w, b1.x, b1.y, b1.z, b1.w};
            #pragma unroll
            for (int i = 0; i < 8; ++i)
                #pragma unroll
                for (int j = 0; j < 8; ++j)
                    acc[i][j] = fmaf(av[i], bv[j], acc[i][j]);
        }
    }

    if (EPI == 0) {
        #pragma unroll
        for (int i = 0; i < 8; ++i) {
            float* cp = C + (size_t)(m0 + tr * 8 + i) * N + n0 + tc * 8;
            *(float4*)cp       = make_float4(acc[i][0], acc[i][1], acc[i][2], acc[i][3]);
            *(float4*)(cp + 4) = make_float4(acc[i][4], acc[i][5], acc[i][6], acc[i][7]);
        }
    } else {
        // f = sel*1024 + h*64 + d ;  target[(b*H+h)*N + n][d]
        const int f0  = n0 + tc * 8;
        const int sel = f0 >> 10;
        const int rem = f0 & 1023;
        const int h   = rem >> 6;
        const int d0  = rem & 63;          // multiple of 8; d0+7 <= 63 (8 | 64)
        float* base = (sel == 0) ? g_q : ((sel == 1) ? g_k : g_v);
        #pragma unroll
        for (int i = 0; i < 8; ++i) {
            const int m = m0 + tr * 8 + i;
            const int b = m >> 11;         // /2048
            const int n = m & 2047;
            float* cp = base + (size_t)(((b * HEADS + h) * NSEQ + n)) * DH + d0;
            *(float4*)cp       = make_float4(acc[i][0], acc[i][1], acc[i][2], acc[i][3]);
            *(float4*)(cp + 4) = make_float4(acc[i][4], acc[i][5], acc[i][6], acc[i][7]);
        }
    }
}

// ---------------------------------------------------------------------------
// Fused RMSNorm + RoPE, in-place on g_q / g_k. One warp per (b,h,n) row of 64.
// grid.y: 0 -> q, 1 -> k.  Interleaved-pair RoPE: (x0,x1) -> (x0*c - x1*s, x1*c + x0*s)
// ---------------------------------------------------------------------------
__global__ __launch_bounds__(256)
void rmsrope_kernel(const float* __restrict__ cosp, const float* __restrict__ sinp,
                    const float* __restrict__ qg, const float* __restrict__ kg)
{
    const int wrow = (blockIdx.x * blockDim.x + threadIdx.x) >> 5;   // global row
    const int lane = threadIdx.x & 31;
    float* arr          = (blockIdx.y == 0) ? g_q : g_k;
    const float* gamma  = (blockIdx.y == 0) ? qg  : kg;

    float* row = arr + (size_t)wrow * DH;
    const int n = wrow & (NSEQ - 1);        // layout (b,h,n,d): n is fastest row index

    float2 x = *(float2*)(row + lane * 2);
    float ss = x.x * x.x + x.y * x.y;
    #pragma unroll
    for (int o = 16; o; o >>= 1) ss += __shfl_xor_sync(0xffffffffu, ss, o);
    const float norm = rsqrtf(ss * (1.0f / 64.0f) + 1e-6f);

    const float g0 = gamma[lane * 2], g1 = gamma[lane * 2 + 1];
    const float q0 = x.x * norm * g0;
    const float q1 = x.y * norm * g1;

    const float* cr = cosp + n * DH + lane * 2;
    const float* sr = sinp + n * DH + lane * 2;
    float2 out;
    out.x = q0 * cr[0] - q1 * sr[0];
    out.y = q1 * cr[1] + q0 * sr[1];
    *(float2*)(row + lane * 2) = out;
}

// ---------------------------------------------------------------------------
// Flash attention, fp32. One block per (64-query tile, b*h). 128 threads.
// Thread grid 16x8: ty owns 4 q rows, tx partitions 64 k-cols (k = kj*8+tx)
// and 8 d-cols (d = tx*8+j). Scale 0.125 folded into Q (exact power of two).
// smem: Qs,Ks,Vs,Ps each [64][68] fp32 -> 69632 B dynamic.
// ---------------------------------------------------------------------------
#define FP_PITCH 68
#define FLASH_SMEM (4 * 64 * FP_PITCH * 4)

__global__ __launch_bounds__(128)
void flash_kernel()
{
    extern __shared__ float sm[];
    float* Qs = sm;
    float* Ks = Qs + 64 * FP_PITCH;
    float* Vs = Ks + 64 * FP_PITCH;
    float* Ps = Vs + 64 * FP_PITCH;

    const int tid = threadIdx.x;
    const int ty  = tid >> 3;      // 0..15
    const int tx  = tid & 7;       // 0..7
    const int q0  = blockIdx.x * 64;
    const int bh  = blockIdx.y;

    const float* Qg = g_q + ((size_t)bh * NSEQ + q0) * DH;
    const float* Kg = g_k + (size_t)bh * NSEQ * DH;
    const float* Vg = g_v + (size_t)bh * NSEQ * DH;

    // Load Q tile, pre-scaled by 1/sqrt(64) = 0.125 (exact)
    #pragma unroll
    for (int r = 0; r < 8; ++r) {
        const int idx = tid + r * 128;          // float4 id 0..1023
        const int i   = idx >> 4;
        const int dq  = (idx & 15) * 4;
        float4 v = *(const float4*)(Qg + i * DH + dq);
        v.x *= 0.125f; v.y *= 0.125f; v.z *= 0.125f; v.w *= 0.125f;
        *(float4*)&Qs[i * FP_PITCH + dq] = v;
    }

    float m_i[4], l_i[4], o[4][8];
    #pragma unroll
    for (int qi = 0; qi < 4; ++qi) {
        m_i[qi] = -CUDART_INF_F;
        l_i[qi] = 0.0f;
        #pragma unroll
        for (int j = 0; j < 8; ++j) o[qi][j] = 0.0f;
    }

    for (int kt = 0; kt < NSEQ / 64; ++kt) {
        __syncthreads();   // previous PV reads done before K/V/P overwrite
        const float* Kt = Kg + (size_t)kt * 64 * DH;
        const float* Vt = Vg + (size_t)kt * 64 * DH;
        #pragma unroll
        for (int r = 0; r < 8; ++r) {
            const int idx = tid + r * 128;
            const int i   = idx >> 4;
            const int dq  = (idx & 15) * 4;
            *(float4*)&Ks[i * FP_PITCH + dq] = *(const float4*)(Kt + i * DH + dq);
            *(float4*)&Vs[i * FP_PITCH + dq] = *(const float4*)(Vt + i * DH + dq);
        }
        __syncthreads();

        // S = Q * K^T  (thread's k columns are kj*8+tx -> conflict-free Ks reads)
        float s[4][8];
        #pragma unroll
        for (int qi = 0; qi < 4; ++qi)
            #pragma unroll
            for (int kj = 0; kj < 8; ++kj) s[qi][kj] = 0.0f;

        #pragma unroll
        for (int db = 0; db < 16; ++db) {
            float4 qf[4], kf[8];
            #pragma unroll
            for (int qi = 0; qi < 4; ++qi)
                qf[qi] = *(const float4*)&Qs[(ty * 4 + qi) * FP_PITCH + db * 4];
            #pragma unroll
            for (int kj = 0; kj < 8; ++kj)
                kf[kj] = *(const float4*)&Ks[(kj * 8 + tx) * FP_PITCH + db * 4];
            #pragma unroll
            for (int qi = 0; qi < 4; ++qi)
                #pragma unroll
                for (int kj = 0; kj < 8; ++kj) {
                    s[qi][kj] = fmaf(qf[qi].x, kf[kj].x, s[qi][kj]);
                    s[qi][kj] = fmaf(qf[qi].y, kf[kj].y, s[qi][kj]);
                    s[qi][kj] = fmaf(qf[qi].z, kf[kj].z, s[qi][kj]);
                    s[qi][kj] = fmaf(qf[qi].w, kf[kj].w, s[qi][kj]);
                }
        }

        // Online softmax per q row (row spread over 8 tx lanes)
        #pragma unroll
        for (int qi = 0; qi < 4; ++qi) {
            float mx = s[qi][0];
            #pragma unroll
            for (int kj = 1; kj < 8; ++kj) mx = fmaxf(mx, s[qi][kj]);
            mx = fmaxf(mx, __shfl_xor_sync(0xffffffffu, mx, 1));
            mx = fmaxf(mx, __shfl_xor_sync(0xffffffffu, mx, 2));
            mx = fmaxf(mx, __shfl_xor_sync(0xffffffffu, mx, 4));

            const float mn    = fmaxf(m_i[qi], mx);
            const float alpha = __expf(m_i[qi] - mn);
            m_i[qi] = mn;

            float rs = 0.0f;
            #pragma unroll
            for (int kj = 0; kj < 8; ++kj) {
                const float p = __expf(s[qi][kj] - mn);
                s[qi][kj] = p;
                rs += p;
            }
            rs += __shfl_xor_sync(0xffffffffu, rs, 1);
            rs += __shfl_xor_sync(0xffffffffu, rs, 2);
            rs += __shfl_xor_sync(0xffffffffu, rs, 4);
            l_i[qi] = l_i[qi] * alpha + rs;

            #pragma unroll
            for (int j = 0; j < 8; ++j) o[qi][j] *= alpha;

            // P[q][k], k = kj*8+tx
            #pragma unroll
            for (int kj = 0; kj < 8; ++kj)
                Ps[(ty * 4 + qi) * FP_PITCH + kj * 8 + tx] = s[qi][kj];
        }
        __syncthreads();

        // O += P * V  (thread owns d = tx*8..tx*8+7)
        #pragma unroll 16
        for (int kk = 0; kk < 64; ++kk) {
            float pf[4];
            #pragma unroll
            for (int qi = 0; qi < 4; ++qi)
                pf[qi] = Ps[(ty * 4 + qi) * FP_PITCH + kk];
            const float4 v0 = *(const float4*)&Vs[kk * FP_PITCH + tx * 8];
            const float4 v1 = *(const float4*)&Vs[kk * FP_PITCH + tx * 8 + 4];
            #pragma unroll
            for (int qi = 0; qi < 4; ++qi) {
                o[qi][0] = fmaf(pf[qi], v0.x, o[qi][0]);
                o[qi][1] = fmaf(pf[qi], v0.y, o[qi][1]);
                o[qi][2] = fmaf(pf[qi], v0.z, o[qi][2]);
                o[qi][3] = fmaf(pf[qi], v0.w, o[qi][3]);
                o[qi][4] = fmaf(pf[qi], v1.x, o[qi][4]);
                o[qi][5] = fmaf(pf[qi], v1.y, o[qi][5]);
                o[qi][6] = fmaf(pf[qi], v1.z, o[qi][6]);
                o[qi][7] = fmaf(pf[qi], v1.w, o[qi][7]);
            }
        }
    }

    // Write O into (b, n, h*64+d) layout for the projection GEMM
    const int b = bh >> 4;
    const int h = bh & 15;
    #pragma unroll
    for (int qi = 0; qi < 4; ++qi) {
        const int n = q0 + ty * 4 + qi;
        const float inv = 1.0f / l_i[qi];
        float* op = g_o + (size_t)(b * NSEQ + n) * CDIM + h * DH + tx * 8;
        *(float4*)op       = make_float4(o[qi][0] * inv, o[qi][1] * inv, o[qi][2] * inv, o[qi][3] * inv);
        *(float4*)(op + 4) = make_float4(o[qi][4] * inv, o[qi][5] * inv, o[qi][6] * inv, o[qi][7] * inv);
    }
}

// ---------------------------------------------------------------------------
// Launch
// ---------------------------------------------------------------------------
extern "C" void kernel_launch(void* const* d_in, const int* in_sizes, int n_in,
                              void* d_out, int out_size)
{
    const float* x      = (const float*)d_in[0];   // (4,2048,1024)
    const float* cosp   = (const float*)d_in[1];   // (1,1,2048,64)
    const float* sinp   = (const float*)d_in[2];
    const float* w_qkv  = (const float*)d_in[3];   // (3072,1024)
    const float* w_proj = (const float*)d_in[4];   // (1024,1024)
    const float* qg     = (const float*)d_in[5];   // (64,)
    const float* kg     = (const float*)d_in[6];   // (64,)
    float* out          = (float*)d_out;           // (4,2048,1024)
    (void)in_sizes; (void)n_in; (void)out_size;

    // Flash kernel needs 68 KB dynamic smem (> 48 KB default); deterministic, capture-safe.
    cudaFuncSetAttribute(flash_kernel, cudaFuncAttributeMaxDynamicSharedMemorySize, FLASH_SMEM);

    void* p_go = nullptr;
    cudaGetSymbolAddress(&p_go, g_o);

    // 1) QKV GEMM with scatter epilogue into g_q/g_k/g_v (B,H,N,D)
    gemm_nt_kernel<1><<<dim3(3 * CDIM / 128, MROWS / 128), 256>>>(x, w_qkv, nullptr, 3 * CDIM, CDIM);

    // 2) RMSNorm + RoPE in-place on q and k
    rmsrope_kernel<<<dim3((2 * BATCH * HEADS * NSEQ) / 16, 2), 256>>>(cosp, sinp, qg, kg);

    // 3) Flash attention -> g_o in (B,N,C) layout
    flash_kernel<<<dim3(NSEQ / 64, BATCH * HEADS), 128, FLASH_SMEM>>>();

    // 4) Output projection -> d_out
    gemm_nt_kernel<0><<<dim3(CDIM / 128, MROWS / 128), 256>>>((const float*)p_go, w_proj, out, CDIM, CDIM);
}

// round 6
// speedup vs baseline: 1.1928x; 1.1928x over previous
#include <cuda_runtime.h>
#include <cuda_bf16.h>
#include <math_constants.h>
#include <cstdint>

// Problem constants
#define BATCH 4
#define NSEQ  2048
#define CDIM  1024
#define HEADS 16
#define DH    64
#define MROWS (BATCH*NSEQ)                 // 8192
#define GK    1024                         // logical inner K of both dense GEMMs
#define KP    3072                         // packed K (3-term split)
#define QKV_ELEMS (BATCH*HEADS*NSEQ*DH)    // 8388608

// Scratch (static device globals; allocation inside kernel_launch is forbidden)
__device__ float g_q[QKV_ELEMS];
__device__ float g_k[QKV_ELEMS];
__device__ float g_v[QKV_ELEMS];
__device__ float g_o[MROWS*CDIM];

// Packed split-bf16 operands: A rows = [hi | lo | hi], B rows = [hi | hi | lo]
__device__ __nv_bfloat16 g_xp [MROWS*KP];     // x packed (A of QKV gemm)
__device__ __nv_bfloat16 g_op [MROWS*KP];     // attention-out packed (A of proj gemm)
__device__ __nv_bfloat16 g_wqp[3*CDIM*KP];    // w_qkv packed (B)
__device__ __nv_bfloat16 g_wpp[CDIM*KP];      // w_proj packed (B)

// ---------------------------------------------------------------------------
// mma.sync helpers (family-target legal: no tcgen05)
// ---------------------------------------------------------------------------
__device__ __forceinline__ uint32_t smem_u32(const void* p) {
    uint32_t a;
    asm("{ .reg .u64 t; cvta.to.shared.u64 t, %1; cvt.u32.u64 %0, t; }" : "=r"(a) : "l"(p));
    return a;
}
__device__ __forceinline__ void ldsm4(uint32_t* r, uint32_t addr) {
    asm volatile("ldmatrix.sync.aligned.m8n8.x4.shared.b16 {%0,%1,%2,%3}, [%4];"
                 : "=r"(r[0]), "=r"(r[1]), "=r"(r[2]), "=r"(r[3]) : "r"(addr));
}
__device__ __forceinline__ void hmma(float* d, const uint32_t* a, const uint32_t* b) {
    asm volatile(
        "mma.sync.aligned.m16n8k16.row.col.f32.bf16.bf16.f32 "
        "{%0,%1,%2,%3}, {%4,%5,%6,%7}, {%8,%9}, {%0,%1,%2,%3};"
        : "+f"(d[0]), "+f"(d[1]), "+f"(d[2]), "+f"(d[3])
        : "r"(a[0]), "r"(a[1]), "r"(a[2]), "r"(a[3]), "r"(b[0]), "r"(b[1]));
}

// FFMA-only exp (no MUFU): exp(x) for x <= 0, rel err ~2.4e-6.
__device__ __forceinline__ float fast_exp(float x) {
    float y = x * 1.4426950408889634f;           // log2(e)
    y = fmaxf(y, -45.0f);                        // clamp: result ~2^-45 ~ 0
    const float C = 12582912.0f;                 // 1.5 * 2^23
    float z  = y + C;
    int   iz = __float_as_int(z);                // low bits: 0x400000 + round(y)
    float fi = z - C;                            // round(y)
    float f  = y - fi;                           // in [-0.5, 0.5]
    float p  = 1.3333558e-3f;                    // ln2^5/120
    p = fmaf(p, f, 9.6181291e-3f);               // ln2^4/24
    p = fmaf(p, f, 5.5504109e-2f);               // ln2^3/6
    p = fmaf(p, f, 2.4022651e-1f);               // ln2^2/2
    p = fmaf(p, f, 6.9314718e-1f);               // ln2
    p = fmaf(p, f, 1.0f);
    int e = ((iz & 0x7FFFFF) - 0x400000) << 23;  // round(y) << 23
    return __int_as_float(__float_as_int(p) + e);
}

// ---------------------------------------------------------------------------
// Pack kernels: fp32 -> packed split-bf16 rows of length KP=3072.
// A pack: [hi | lo | hi]    B pack: [hi | hi | lo]
// (A'·B'^T over K'=3072  ==  Ahi·Bhi + Alo·Bhi + Ahi·Blo)
// ---------------------------------------------------------------------------
__global__ __launch_bounds__(256)
void pack_a_kernel(const float* __restrict__ src, __nv_bfloat16* __restrict__ dst, int nelem)
{
    const int i = blockIdx.x * blockDim.x + threadIdx.x;
    if (i >= nelem) return;
    const int m = i >> 10, k = i & 1023;
    const float v = src[i];
    const __nv_bfloat16 h = __float2bfloat16(v);
    const __nv_bfloat16 l = __float2bfloat16(v - __bfloat162float(h));
    __nv_bfloat16* row = dst + (size_t)m * KP;
    row[k] = h; row[k + 1024] = l; row[k + 2048] = h;
}
__global__ __launch_bounds__(256)
void pack_b_kernel(const float* __restrict__ src, __nv_bfloat16* __restrict__ dst, int nelem)
{
    const int i = blockIdx.x * blockDim.x + threadIdx.x;
    if (i >= nelem) return;
    const int m = i >> 10, k = i & 1023;
    const float v = src[i];
    const __nv_bfloat16 h = __float2bfloat16(v);
    const __nv_bfloat16 l = __float2bfloat16(v - __bfloat162float(h));
    __nv_bfloat16* row = dst + (size_t)m * KP;
    row[k] = h; row[k + 1024] = h; row[k + 2048] = l;
}

// ---------------------------------------------------------------------------
// Tensor-core NT GEMM via mma.sync: C[m,n] = sum_k A[m,k]*B[n,k], bf16 in, f32 acc.
// K = KP = 3072. Tile 128x128, BK=32, 256 threads, warp grid 2x4 (warp tile 64x32).
// smem pitch 56 bf16 (112B): 16B-aligned rows, conflict-free ldmatrix.
// EPI==0: plain write. EPI==1: QKV scatter into g_q/g_k/g_v (B,H,N,D).
// ---------------------------------------------------------------------------
#define GPITCH 56                      // bf16 units
#define GTILE_B (128*GPITCH*2)         // 14336 B per operand tile
#define GSTAGE_B (2*GTILE_B)           // 28672 B per stage (A+B)
#define GSMEM (2*GSTAGE_B)             // 57344 B

template<int EPI>
__global__ __launch_bounds__(256, 2)
void gemm_mma(const __nv_bfloat16* __restrict__ Ap, const __nv_bfloat16* __restrict__ Bp,
              float* __restrict__ C, int Nglob)
{
    extern __shared__ char smem[];
    const uint32_t sbase = smem_u32(smem);

    const int tid  = threadIdx.x;
    const int wid  = tid >> 5;
    const int lane = tid & 31;
    const int wm   = wid & 1;          // m warp coord (x64)
    const int wn   = wid >> 1;         // n warp coord (x32)
    const int m0   = blockIdx.y * 128;
    const int n0   = blockIdx.x * 128;

    // global staging: 512 16B-quads per operand; thread handles quad tid and tid+256
    const int lr = tid >> 2;           // row 0..63 (and +64)
    const int lq = tid & 3;            // 16B quad within 64B row-chunk
    const __nv_bfloat16* Ag = Ap + (size_t)(m0 + lr) * KP + lq * 8;
    const __nv_bfloat16* Bg = Bp + (size_t)(n0 + lr) * KP + lq * 8;
    const size_t rstep = (size_t)64 * KP;

    // per-thread ldmatrix byte offsets (within a stage)
    const uint32_t a_off = (uint32_t)((wm*64 + (lane & 15)) * 112 + (lane >> 4) * 16);
    const uint32_t b_off = (uint32_t)((wn*32 + (lane & 7) + ((lane >> 4) << 3)) * 112
                                      + ((lane >> 3) & 1) * 16);

    float acc[4][4][4];
    #pragma unroll
    for (int mi = 0; mi < 4; ++mi)
        #pragma unroll
        for (int nf = 0; nf < 4; ++nf)
            #pragma unroll
            for (int j = 0; j < 4; ++j) acc[mi][nf][j] = 0.0f;

    // prologue: load iter 0 and store to stage 0
    uint4 ra0 = *(const uint4*)Ag;
    uint4 ra1 = *(const uint4*)(Ag + rstep);
    uint4 rb0 = *(const uint4*)Bg;
    uint4 rb1 = *(const uint4*)(Bg + rstep);
    {
        char* s = smem;
        *(uint4*)(s + lr*112 + lq*16)            = ra0;
        *(uint4*)(s + (lr+64)*112 + lq*16)       = ra1;
        *(uint4*)(s + GTILE_B + lr*112 + lq*16)      = rb0;
        *(uint4*)(s + GTILE_B + (lr+64)*112 + lq*16) = rb1;
    }
    __syncthreads();

    const int T = KP / 32;             // 96
    #pragma unroll 1
    for (int t = 0; t < T; ++t) {
        if (t + 1 < T) {               // prefetch next K-slab to registers
            const __nv_bfloat16* An = Ag + (t + 1) * 32;
            const __nv_bfloat16* Bn = Bg + (t + 1) * 32;
            ra0 = *(const uint4*)An;
            ra1 = *(const uint4*)(An + rstep);
            rb0 = *(const uint4*)Bn;
            rb1 = *(const uint4*)(Bn + rstep);
        }

        const uint32_t sA = sbase + (t & 1) * GSTAGE_B;
        const uint32_t sB = sA + GTILE_B;
        #pragma unroll
        for (int ks = 0; ks < 2; ++ks) {
            uint32_t a[4][4], b[2][4];
            #pragma unroll
            for (int mi = 0; mi < 4; ++mi)
                ldsm4(a[mi], sA + a_off + mi * 1792 + ks * 32);
            #pragma unroll
            for (int np = 0; np < 2; ++np)
                ldsm4(b[np], sB + b_off + np * 1792 + ks * 32);
            #pragma unroll
            for (int mi = 0; mi < 4; ++mi) {
                hmma(acc[mi][0], a[mi], &b[0][0]);
                hmma(acc[mi][1], a[mi], &b[0][2]);
                hmma(acc[mi][2], a[mi], &b[1][0]);
                hmma(acc[mi][3], a[mi], &b[1][2]);
            }
        }

        if (t + 1 < T) {
            char* s = smem + ((t + 1) & 1) * GSTAGE_B;
            *(uint4*)(s + lr*112 + lq*16)            = ra0;
            *(uint4*)(s + (lr+64)*112 + lq*16)       = ra1;
            *(uint4*)(s + GTILE_B + lr*112 + lq*16)      = rb0;
            *(uint4*)(s + GTILE_B + (lr+64)*112 + lq*16) = rb1;
            __syncthreads();
        }
    }

    // Epilogue: acc[mi][nf]: rows r0 = m0+wm*64+mi*16+(lane>>2), r1=r0+8;
    //           cols c = n0+wn*32+nf*8+(lane&3)*2 (even).
    const int rbase = m0 + wm * 64 + (lane >> 2);
    const int cbase = n0 + wn * 32 + (lane & 3) * 2;
    #pragma unroll
    for (int mi = 0; mi < 4; ++mi) {
        #pragma unroll
        for (int nf = 0; nf < 4; ++nf) {
            const int r0 = rbase + mi * 16;
            const int c  = cbase + nf * 8;
            const float2 v01 = make_float2(acc[mi][nf][0], acc[mi][nf][1]);
            const float2 v23 = make_float2(acc[mi][nf][2], acc[mi][nf][3]);
            if (EPI == 0) {
                *(float2*)(C + (size_t)r0 * Nglob + c)       = v01;
                *(float2*)(C + (size_t)(r0 + 8) * Nglob + c) = v23;
            } else {
                // f = sel*1024 + h*64 + d ; target[(b*H+h)*N + n][d]
                const int sel = c >> 10;
                const int rem = c & 1023;
                const int h   = rem >> 6;
                const int dcl = rem & 63;     // even; dcl+1 stays in head
                float* base = (sel == 0) ? g_q : ((sel == 1) ? g_k : g_v);
                {
                    const int m = r0, b = m >> 11, n = m & 2047;
                    *(float2*)(base + (size_t)((b * HEADS + h) * NSEQ + n) * DH + dcl) = v01;
                }
                {
                    const int m = r0 + 8, b = m >> 11, n = m & 2047;
                    *(float2*)(base + (size_t)((b * HEADS + h) * NSEQ + n) * DH + dcl) = v23;
                }
            }
        }
    }
}

// ---------------------------------------------------------------------------
// Fused RMSNorm + RoPE, in-place on g_q / g_k. One warp per (b,h,n) row of 64.
// ---------------------------------------------------------------------------
__global__ __launch_bounds__(256)
void rmsrope_kernel(const float* __restrict__ cosp, const float* __restrict__ sinp,
                    const float* __restrict__ qg, const float* __restrict__ kg)
{
    const int wrow = (blockIdx.x * blockDim.x + threadIdx.x) >> 5;
    const int lane = threadIdx.x & 31;
    float* arr         = (blockIdx.y == 0) ? g_q : g_k;
    const float* gamma = (blockIdx.y == 0) ? qg  : kg;

    float* row = arr + (size_t)wrow * DH;
    const int n = wrow & (NSEQ - 1);

    float2 x = *(float2*)(row + lane * 2);
    float ss = x.x * x.x + x.y * x.y;
    #pragma unroll
    for (int o = 16; o; o >>= 1) ss += __shfl_xor_sync(0xffffffffu, ss, o);
    const float norm = rsqrtf(ss * (1.0f / 64.0f) + 1e-6f);

    const float g0 = gamma[lane * 2], g1 = gamma[lane * 2 + 1];
    const float q0 = x.x * norm * g0;
    const float q1 = x.y * norm * g1;

    const float* cr = cosp + n * DH + lane * 2;
    const float* sr = sinp + n * DH + lane * 2;
    float2 out;
    out.x = q0 * cr[0] - q1 * sr[0];
    out.y = q1 * cr[1] + q0 * sr[1];
    *(float2*)(row + lane * 2) = out;
}

// ---------------------------------------------------------------------------
// Flash attention, fp32 SIMT, MUFU-free softmax (fast_exp on fma pipe).
// One block per (64-query tile, b*h). 128 threads. Structure identical to the
// R3-passing kernel except __expf -> fast_exp.
// ---------------------------------------------------------------------------
#define FP_PITCH 68
#define FLASH_SMEM (4 * 64 * FP_PITCH * 4)

__global__ __launch_bounds__(128)
void flash_kernel()
{
    extern __shared__ float sm[];
    float* Qs = sm;
    float* Ks = Qs + 64 * FP_PITCH;
    float* Vs = Ks + 64 * FP_PITCH;
    float* Ps = Vs + 64 * FP_PITCH;

    const int tid = threadIdx.x;
    const int ty  = tid >> 3;
    const int tx  = tid & 7;
    const int q0  = blockIdx.x * 64;
    const int bh  = blockIdx.y;

    const float* Qg = g_q + ((size_t)bh * NSEQ + q0) * DH;
    const float* Kg = g_k + (size_t)bh * NSEQ * DH;
    const float* Vg = g_v + (size_t)bh * NSEQ * DH;

    #pragma unroll
    for (int r = 0; r < 8; ++r) {
        const int idx = tid + r * 128;
        const int i   = idx >> 4;
        const int dq  = (idx & 15) * 4;
        float4 v = *(const float4*)(Qg + i * DH + dq);
        v.x *= 0.125f; v.y *= 0.125f; v.z *= 0.125f; v.w *= 0.125f;
        *(float4*)&Qs[i * FP_PITCH + dq] = v;
    }

    float m_i[4], l_i[4], o[4][8];
    #pragma unroll
    for (int qi = 0; qi < 4; ++qi) {
        m_i[qi] = -CUDART_INF_F;
        l_i[qi] = 0.0f;
        #pragma unroll
        for (int j = 0; j < 8; ++j) o[qi][j] = 0.0f;
    }

    for (int kt = 0; kt < NSEQ / 64; ++kt) {
        __syncthreads();
        const float* Kt = Kg + (size_t)kt * 64 * DH;
        const float* Vt = Vg + (size_t)kt * 64 * DH;
        #pragma unroll
        for (int r = 0; r < 8; ++r) {
            const int idx = tid + r * 128;
            const int i   = idx >> 4;
            const int dq  = (idx & 15) * 4;
            *(float4*)&Ks[i * FP_PITCH + dq] = *(const float4*)(Kt + i * DH + dq);
            *(float4*)&Vs[i * FP_PITCH + dq] = *(const float4*)(Vt + i * DH + dq);
        }
        __syncthreads();

        float s[4][8];
        #pragma unroll
        for (int qi = 0; qi < 4; ++qi)
            #pragma unroll
            for (int kj = 0; kj < 8; ++kj) s[qi][kj] = 0.0f;

        #pragma unroll
        for (int db = 0; db < 16; ++db) {
            float4 qf[4], kf[8];
            #pragma unroll
            for (int qi = 0; qi < 4; ++qi)
                qf[qi] = *(const float4*)&Qs[(ty * 4 + qi) * FP_PITCH + db * 4];
            #pragma unroll
            for (int kj = 0; kj < 8; ++kj)
                kf[kj] = *(const float4*)&Ks[(kj * 8 + tx) * FP_PITCH + db * 4];
            #pragma unroll
            for (int qi = 0; qi < 4; ++qi)
                #pragma unroll
                for (int kj = 0; kj < 8; ++kj) {
                    s[qi][kj] = fmaf(qf[qi].x, kf[kj].x, s[qi][kj]);
                    s[qi][kj] = fmaf(qf[qi].y, kf[kj].y, s[qi][kj]);
                    s[qi][kj] = fmaf(qf[qi].z, kf[kj].z, s[qi][kj]);
                    s[qi][kj] = fmaf(qf[qi].w, kf[kj].w, s[qi][kj]);
                }
        }

        #pragma unroll
        for (int qi = 0; qi < 4; ++qi) {
            float mx = s[qi][0];
            #pragma unroll
            for (int kj = 1; kj < 8; ++kj) mx = fmaxf(mx, s[qi][kj]);
            mx = fmaxf(mx, __shfl_xor_sync(0xffffffffu, mx, 1));
            mx = fmaxf(mx, __shfl_xor_sync(0xffffffffu, mx, 2));
            mx = fmaxf(mx, __shfl_xor_sync(0xffffffffu, mx, 4));

            const float mn    = fmaxf(m_i[qi], mx);
            const float alpha = fast_exp(m_i[qi] - mn);
            m_i[qi] = mn;

            float rs = 0.0f;
            #pragma unroll
            for (int kj = 0; kj < 8; ++kj) {
                const float p = fast_exp(s[qi][kj] - mn);
                s[qi][kj] = p;
                rs += p;
            }
            rs += __shfl_xor_sync(0xffffffffu, rs, 1);
            rs += __shfl_xor_sync(0xffffffffu, rs, 2);
            rs += __shfl_xor_sync(0xffffffffu, rs, 4);
            l_i[qi] = l_i[qi] * alpha + rs;

            #pragma unroll
            for (int j = 0; j < 8; ++j) o[qi][j] *= alpha;

            #pragma unroll
            for (int kj = 0; kj < 8; ++kj)
                Ps[(ty * 4 + qi) * FP_PITCH + kj * 8 + tx] = s[qi][kj];
        }
        __syncthreads();

        #pragma unroll 16
        for (int kk = 0; kk < 64; ++kk) {
            float pf[4];
            #pragma unroll
            for (int qi = 0; qi < 4; ++qi)
                pf[qi] = Ps[(ty * 4 + qi) * FP_PITCH + kk];
            const float4 v0 = *(const float4*)&Vs[kk * FP_PITCH + tx * 8];
            const float4 v1 = *(const float4*)&Vs[kk * FP_PITCH + tx * 8 + 4];
            #pragma unroll
            for (int qi = 0; qi < 4; ++qi) {
                o[qi][0] = fmaf(pf[qi], v0.x, o[qi][0]);
                o[qi][1] = fmaf(pf[qi], v0.y, o[qi][1]);
                o[qi][2] = fmaf(pf[qi], v0.z, o[qi][2]);
                o[qi][3] = fmaf(pf[qi], v0.w, o[qi][3]);
                o[qi][4] = fmaf(pf[qi], v1.x, o[qi][4]);
                o[qi][5] = fmaf(pf[qi], v1.y, o[qi][5]);
                o[qi][6] = fmaf(pf[qi], v1.z, o[qi][6]);
                o[qi][7] = fmaf(pf[qi], v1.w, o[qi][7]);
            }
        }
    }

    const int b = bh >> 4;
    const int h = bh & 15;
    #pragma unroll
    for (int qi = 0; qi < 4; ++qi) {
        const int n = q0 + ty * 4 + qi;
        const float inv = 1.0f / l_i[qi];
        float* op = g_o + (size_t)(b * NSEQ + n) * CDIM + h * DH + tx * 8;
        *(float4*)op       = make_float4(o[qi][0] * inv, o[qi][1] * inv, o[qi][2] * inv, o[qi][3] * inv);
        *(float4*)(op + 4) = make_float4(o[qi][4] * inv, o[qi][5] * inv, o[qi][6] * inv, o[qi][7] * inv);
    }
}

// ---------------------------------------------------------------------------
// Launch
// ---------------------------------------------------------------------------
extern "C" void kernel_launch(void* const* d_in, const int* in_sizes, int n_in,
                              void* d_out, int out_size)
{
    const float* x      = (const float*)d_in[0];
    const float* cosp   = (const float*)d_in[1];
    const float* sinp   = (const float*)d_in[2];
    const float* w_qkv  = (const float*)d_in[3];
    const float* w_proj = (const float*)d_in[4];
    const float* qg     = (const float*)d_in[5];
    const float* kg     = (const float*)d_in[6];
    float* out          = (float*)d_out;
    (void)in_sizes; (void)n_in; (void)out_size;

    cudaFuncSetAttribute(flash_kernel, cudaFuncAttributeMaxDynamicSharedMemorySize, FLASH_SMEM);
    cudaFuncSetAttribute(gemm_mma<0>, cudaFuncAttributeMaxDynamicSharedMemorySize, GSMEM);
    cudaFuncSetAttribute(gemm_mma<1>, cudaFuncAttributeMaxDynamicSharedMemorySize, GSMEM);

    void *p_go, *p_xp, *p_op, *p_wqp, *p_wpp;
    cudaGetSymbolAddress(&p_go,  g_o);
    cudaGetSymbolAddress(&p_xp,  g_xp);
    cudaGetSymbolAddress(&p_op,  g_op);
    cudaGetSymbolAddress(&p_wqp, g_wqp);
    cudaGetSymbolAddress(&p_wpp, g_wpp);

    // 0) Pack operands into split-bf16 [hi|lo|hi] / [hi|hi|lo] rows (K'=3072)
    pack_a_kernel<<<(MROWS*GK  + 255)/256, 256>>>(x,      (__nv_bfloat16*)p_xp,  MROWS*GK);
    pack_b_kernel<<<(3*CDIM*GK + 255)/256, 256>>>(w_qkv,  (__nv_bfloat16*)p_wqp, 3*CDIM*GK);
    pack_b_kernel<<<(CDIM*GK   + 255)/256, 256>>>(w_proj, (__nv_bfloat16*)p_wpp, CDIM*GK);

    // 1) QKV GEMM (HMMA tensor cores) with scatter epilogue into g_q/g_k/g_v
    gemm_mma<1><<<dim3(3*CDIM/128, MROWS/128), 256, GSMEM>>>(
        (const __nv_bfloat16*)p_xp, (const __nv_bfloat16*)p_wqp, nullptr, 3*CDIM);

    // 2) RMSNorm + RoPE in-place
    rmsrope_kernel<<<dim3((2*BATCH*HEADS*NSEQ)/16, 2), 256>>>(cosp, sinp, qg, kg);

    // 3) Flash attention -> g_o (B,N,C)
    flash_kernel<<<dim3(NSEQ/64, BATCH*HEADS), 128, FLASH_SMEM>>>();

    // 4) Pack attention output, then projection GEMM (HMMA)
    pack_a_kernel<<<(MROWS*GK + 255)/256, 256>>>((const float*)p_go, (__nv_bfloat16*)p_op, MROWS*GK);
    gemm_mma<0><<<dim3(CDIM/128, MROWS/128), 256, GSMEM>>>(
        (const __nv_bfloat16*)p_op, (const __nv_bfloat16*)p_wpp, out, CDIM);
}

// round 7
// speedup vs baseline: 1.8691x; 1.5670x over previous
#include <cuda_runtime.h>
#include <cuda_bf16.h>
#include <math_constants.h>
#include <cstdint>

// Problem constants
#define BATCH 4
#define NSEQ  2048
#define CDIM  1024
#define HEADS 16
#define DH    64
#define MROWS (BATCH*NSEQ)                 // 8192
#define GK    1024                         // logical inner K of dense GEMMs
#define KP    3072                         // packed K (3-term split)
#define KQ    192                          // packed head dim (3-term split)
#define QKV_ELEMS (BATCH*HEADS*NSEQ*DH)    // 8388608

// Scratch (static device globals; allocation inside kernel_launch is forbidden)
__device__ float g_q[QKV_ELEMS];
__device__ float g_k[QKV_ELEMS];
__device__ float g_v[QKV_ELEMS];
__device__ float g_o[MROWS*CDIM];

// Packed split-bf16 operands for dense GEMMs
__device__ __nv_bfloat16 g_xp [MROWS*KP];     // x packed (A of QKV gemm)
__device__ __nv_bfloat16 g_op [MROWS*KP];     // attention-out packed (A of proj gemm)
__device__ __nv_bfloat16 g_wqp[3*CDIM*KP];    // w_qkv packed (B)
__device__ __nv_bfloat16 g_wpp[CDIM*KP];      // w_proj packed (B)

// Flash operands: packed Q/K (b,h,n,192), transposed split V (b,h,d,n)
__device__ __nv_bfloat16 g_qp  [BATCH*HEADS*NSEQ*KQ];
__device__ __nv_bfloat16 g_kp  [BATCH*HEADS*NSEQ*KQ];
__device__ __nv_bfloat16 g_vthi[BATCH*HEADS*DH*NSEQ];
__device__ __nv_bfloat16 g_vtlo[BATCH*HEADS*DH*NSEQ];

// ---------------------------------------------------------------------------
// mma.sync helpers (family-target legal)
// ---------------------------------------------------------------------------
__device__ __forceinline__ uint32_t smem_u32(const void* p) {
    uint32_t a;
    asm("{ .reg .u64 t; cvta.to.shared.u64 t, %1; cvt.u32.u64 %0, t; }" : "=r"(a) : "l"(p));
    return a;
}
__device__ __forceinline__ void ldsm4(uint32_t* r, uint32_t addr) {
    asm volatile("ldmatrix.sync.aligned.m8n8.x4.shared.b16 {%0,%1,%2,%3}, [%4];"
                 : "=r"(r[0]), "=r"(r[1]), "=r"(r[2]), "=r"(r[3]) : "r"(addr));
}
__device__ __forceinline__ void hmma(float* d, const uint32_t* a, const uint32_t* b) {
    asm volatile(
        "mma.sync.aligned.m16n8k16.row.col.f32.bf16.bf16.f32 "
        "{%0,%1,%2,%3}, {%4,%5,%6,%7}, {%8,%9}, {%0,%1,%2,%3};"
        : "+f"(d[0]), "+f"(d[1]), "+f"(d[2]), "+f"(d[3])
        : "r"(a[0]), "r"(a[1]), "r"(a[2]), "r"(a[3]), "r"(b[0]), "r"(b[1]));
}
// pack two fp32 -> bf16x2 {lo=e0, hi=e1}
__device__ __forceinline__ uint32_t pk2(float e0, float e1) {
    uint32_t r;
    asm("cvt.rn.bf16x2.f32 %0, %1, %2;" : "=r"(r) : "f"(e1), "f"(e0));
    return r;
}

// FFMA-only exp (no MUFU): exp(x) for x <= 0, rel err ~2.4e-6.
__device__ __forceinline__ float fast_exp(float x) {
    float y = x * 1.4426950408889634f;
    y = fmaxf(y, -45.0f);
    const float C = 12582912.0f;                 // 1.5 * 2^23
    float z  = y + C;
    int   iz = __float_as_int(z);
    float fi = z - C;
    float f  = y - fi;
    float p  = 1.3333558e-3f;
    p = fmaf(p, f, 9.6181291e-3f);
    p = fmaf(p, f, 5.5504109e-2f);
    p = fmaf(p, f, 2.4022651e-1f);
    p = fmaf(p, f, 6.9314718e-1f);
    p = fmaf(p, f, 1.0f);
    int e = ((iz & 0x7FFFFF) - 0x400000) << 23;
    return __int_as_float(__float_as_int(p) + e);
}

// ---------------------------------------------------------------------------
// Pack kernels (dense GEMM operands): A=[hi|lo|hi], B=[hi|hi|lo], K'=3072.
// ---------------------------------------------------------------------------
__global__ __launch_bounds__(256)
void pack_a_kernel(const float* __restrict__ src, __nv_bfloat16* __restrict__ dst, int nelem)
{
    const int i = blockIdx.x * blockDim.x + threadIdx.x;
    if (i >= nelem) return;
    const int m = i >> 10, k = i & 1023;
    const float v = src[i];
    const __nv_bfloat16 h = __float2bfloat16(v);
    const __nv_bfloat16 l = __float2bfloat16(v - __bfloat162float(h));
    __nv_bfloat16* row = dst + (size_t)m * KP;
    row[k] = h; row[k + 1024] = l; row[k + 2048] = h;
}
__global__ __launch_bounds__(256)
void pack_b_kernel(const float* __restrict__ src, __nv_bfloat16* __restrict__ dst, int nelem)
{
    const int i = blockIdx.x * blockDim.x + threadIdx.x;
    if (i >= nelem) return;
    const int m = i >> 10, k = i & 1023;
    const float v = src[i];
    const __nv_bfloat16 h = __float2bfloat16(v);
    const __nv_bfloat16 l = __float2bfloat16(v - __bfloat162float(h));
    __nv_bfloat16* row = dst + (size_t)m * KP;
    row[k] = h; row[k + 1024] = h; row[k + 2048] = l;
}

// ---------------------------------------------------------------------------
// Dense NT GEMM via mma.sync (unchanged from passing R5 kernel).
// ---------------------------------------------------------------------------
#define GPITCH 56
#define GTILE_B (128*GPITCH*2)
#define GSTAGE_B (2*GTILE_B)
#define GSMEM (2*GSTAGE_B)

template<int EPI>
__global__ __launch_bounds__(256, 2)
void gemm_mma(const __nv_bfloat16* __restrict__ Ap, const __nv_bfloat16* __restrict__ Bp,
              float* __restrict__ C, int Nglob)
{
    extern __shared__ char smem[];
    const uint32_t sbase = smem_u32(smem);

    const int tid  = threadIdx.x;
    const int wid  = tid >> 5;
    const int lane = tid & 31;
    const int wm   = wid & 1;
    const int wn   = wid >> 1;
    const int m0   = blockIdx.y * 128;
    const int n0   = blockIdx.x * 128;

    const int lr = tid >> 2;
    const int lq = tid & 3;
    const __nv_bfloat16* Ag = Ap + (size_t)(m0 + lr) * KP + lq * 8;
    const __nv_bfloat16* Bg = Bp + (size_t)(n0 + lr) * KP + lq * 8;
    const size_t rstep = (size_t)64 * KP;

    const uint32_t a_off = (uint32_t)((wm*64 + (lane & 15)) * 112 + (lane >> 4) * 16);
    const uint32_t b_off = (uint32_t)((wn*32 + (lane & 7) + ((lane >> 4) << 3)) * 112
                                      + ((lane >> 3) & 1) * 16);

    float acc[4][4][4];
    #pragma unroll
    for (int mi = 0; mi < 4; ++mi)
        #pragma unroll
        for (int nf = 0; nf < 4; ++nf)
            #pragma unroll
            for (int j = 0; j < 4; ++j) acc[mi][nf][j] = 0.0f;

    uint4 ra0 = *(const uint4*)Ag;
    uint4 ra1 = *(const uint4*)(Ag + rstep);
    uint4 rb0 = *(const uint4*)Bg;
    uint4 rb1 = *(const uint4*)(Bg + rstep);
    {
        char* s = smem;
        *(uint4*)(s + lr*112 + lq*16)            = ra0;
        *(uint4*)(s + (lr+64)*112 + lq*16)       = ra1;
        *(uint4*)(s + GTILE_B + lr*112 + lq*16)      = rb0;
        *(uint4*)(s + GTILE_B + (lr+64)*112 + lq*16) = rb1;
    }
    __syncthreads();

    const int T = KP / 32;
    #pragma unroll 1
    for (int t = 0; t < T; ++t) {
        if (t + 1 < T) {
            const __nv_bfloat16* An = Ag + (t + 1) * 32;
            const __nv_bfloat16* Bn = Bg + (t + 1) * 32;
            ra0 = *(const uint4*)An;
            ra1 = *(const uint4*)(An + rstep);
            rb0 = *(const uint4*)Bn;
            rb1 = *(const uint4*)(Bn + rstep);
        }

        const uint32_t sA = sbase + (t & 1) * GSTAGE_B;
        const uint32_t sB = sA + GTILE_B;
        #pragma unroll
        for (int ks = 0; ks < 2; ++ks) {
            uint32_t a[4][4], b[2][4];
            #pragma unroll
            for (int mi = 0; mi < 4; ++mi)
                ldsm4(a[mi], sA + a_off + mi * 1792 + ks * 32);
            #pragma unroll
            for (int np = 0; np < 2; ++np)
                ldsm4(b[np], sB + b_off + np * 1792 + ks * 32);
            #pragma unroll
            for (int mi = 0; mi < 4; ++mi) {
                hmma(acc[mi][0], a[mi], &b[0][0]);
                hmma(acc[mi][1], a[mi], &b[0][2]);
                hmma(acc[mi][2], a[mi], &b[1][0]);
                hmma(acc[mi][3], a[mi], &b[1][2]);
            }
        }

        if (t + 1 < T) {
            char* s = smem + ((t + 1) & 1) * GSTAGE_B;
            *(uint4*)(s + lr*112 + lq*16)            = ra0;
            *(uint4*)(s + (lr+64)*112 + lq*16)       = ra1;
            *(uint4*)(s + GTILE_B + lr*112 + lq*16)      = rb0;
            *(uint4*)(s + GTILE_B + (lr+64)*112 + lq*16) = rb1;
            __syncthreads();
        }
    }

    const int rbase = m0 + wm * 64 + (lane >> 2);
    const int cbase = n0 + wn * 32 + (lane & 3) * 2;
    #pragma unroll
    for (int mi = 0; mi < 4; ++mi) {
        #pragma unroll
        for (int nf = 0; nf < 4; ++nf) {
            const int r0 = rbase + mi * 16;
            const int c  = cbase + nf * 8;
            const float2 v01 = make_float2(acc[mi][nf][0], acc[mi][nf][1]);
            const float2 v23 = make_float2(acc[mi][nf][2], acc[mi][nf][3]);
            if (EPI == 0) {
                *(float2*)(C + (size_t)r0 * Nglob + c)       = v01;
                *(float2*)(C + (size_t)(r0 + 8) * Nglob + c) = v23;
            } else {
                const int sel = c >> 10;
                const int rem = c & 1023;
                const int h   = rem >> 6;
                const int dcl = rem & 63;
                float* base = (sel == 0) ? g_q : ((sel == 1) ? g_k : g_v);
                {
                    const int m = r0, b = m >> 11, n = m & 2047;
                    *(float2*)(base + (size_t)((b * HEADS + h) * NSEQ + n) * DH + dcl) = v01;
                }
                {
                    const int m = r0 + 8, b = m >> 11, n = m & 2047;
                    *(float2*)(base + (size_t)((b * HEADS + h) * NSEQ + n) * DH + dcl) = v23;
                }
            }
        }
    }
}

// ---------------------------------------------------------------------------
// Fused RMSNorm + RoPE + split-bf16 pack.
// Reads fp32 g_q/g_k, writes packed rows of 192 bf16:
//   q: [hi|lo|hi] with 0.125 score scale folded in;  k: [hi|hi|lo].
// One warp per (b,h,n) row.
// ---------------------------------------------------------------------------
__global__ __launch_bounds__(256)
void rmsrope_pack_kernel(const float* __restrict__ cosp, const float* __restrict__ sinp,
                         const float* __restrict__ qg, const float* __restrict__ kg)
{
    const int wrow = (blockIdx.x * blockDim.x + threadIdx.x) >> 5;
    const int lane = threadIdx.x & 31;
    const int isq  = (blockIdx.y == 0);
    const float* arr   = isq ? g_q : g_k;
    const float* gamma = isq ? qg  : kg;

    const float* row = arr + (size_t)wrow * DH;
    const int n = wrow & (NSEQ - 1);

    float2 x = *(const float2*)(row + lane * 2);
    float ss = x.x * x.x + x.y * x.y;
    #pragma unroll
    for (int o = 16; o; o >>= 1) ss += __shfl_xor_sync(0xffffffffu, ss, o);
    const float norm = rsqrtf(ss * (1.0f / 64.0f) + 1e-6f);

    const float g0 = gamma[lane * 2], g1 = gamma[lane * 2 + 1];
    const float q0 = x.x * norm * g0;
    const float q1 = x.y * norm * g1;

    const float* cr = cosp + n * DH + lane * 2;
    const float* sr = sinp + n * DH + lane * 2;
    const float scale = isq ? 0.125f : 1.0f;
    const float v0 = (q0 * cr[0] - q1 * sr[0]) * scale;
    const float v1 = (q1 * cr[1] + q0 * sr[1]) * scale;

    const float h0 = __bfloat162float(__float2bfloat16(v0));
    const float h1 = __bfloat162float(__float2bfloat16(v1));
    const uint32_t HP = pk2(v0, v1);               // rounds to bf16 pair
    const uint32_t LP = pk2(v0 - h0, v1 - h1);

    uint32_t* dst = (uint32_t*)((isq ? g_qp : g_kp) + (size_t)wrow * KQ);
    if (isq) { dst[lane] = HP; dst[32 + lane] = LP; dst[64 + lane] = HP; }
    else     { dst[lane] = HP; dst[32 + lane] = HP; dst[64 + lane] = LP; }
}

// ---------------------------------------------------------------------------
// V transpose + split: fp32 g_v (bh,n,d) -> bf16 g_vthi/g_vtlo (bh,d,n).
// Block: one (bh, 64-n tile). smem 64x68 fp32 transpose.
// ---------------------------------------------------------------------------
__global__ __launch_bounds__(128)
void vtrans_kernel()
{
    __shared__ float s[64 * 68];
    const int tid = threadIdx.x;
    const int n0  = blockIdx.x * 64;
    const int bh  = blockIdx.y;
    const float* src = g_v + ((size_t)bh * NSEQ + n0) * DH;

    #pragma unroll
    for (int it = 0; it < 8; ++it) {
        const int idx = tid + it * 128;     // 1024 float4 quads
        const int n = idx >> 4, q = (idx & 15) * 4;
        *(float4*)&s[n * 68 + q] = *(const float4*)(src + (size_t)n * DH + q);
    }
    __syncthreads();

    const int d  = tid >> 1;
    const int nh = (tid & 1) * 32;
    uint32_t hibuf[16], lobuf[16];
    #pragma unroll
    for (int j = 0; j < 16; ++j) {
        const float a = s[(nh + 2*j) * 68 + d];
        const float b = s[(nh + 2*j + 1) * 68 + d];
        const float ha = __bfloat162float(__float2bfloat16(a));
        const float hb = __bfloat162float(__float2bfloat16(b));
        hibuf[j] = pk2(a, b);
        lobuf[j] = pk2(a - ha, b - hb);
    }
    uint32_t* dh = (uint32_t*)(g_vthi + ((size_t)bh * DH + d) * NSEQ + n0 + nh);
    uint32_t* dl = (uint32_t*)(g_vtlo + ((size_t)bh * DH + d) * NSEQ + n0 + nh);
    #pragma unroll
    for (int j = 0; j < 16; ++j) { dh[j] = hibuf[j]; dl[j] = lobuf[j]; }
}

// ---------------------------------------------------------------------------
// Flash attention via mma.sync (FA2 style).
// Block: 64 q-rows x one bh, 4 warps; warp w owns q rows 16w..16w+15.
// S = Qp(64x192) * Kp(64x192)^T  (3-term split packed along k').
// softmax in registers (fast_exp), P repacked to bf16 hi/lo A-frags in regs.
// O += Phi*Vhi + Plo*Vhi + Phi*Vlo  with V^T hi/lo tiles from smem.
// smem: Qs 64x400B, Ks 64x400B, Vh 64x144B, Vl 64x144B = 69632 B.
// ---------------------------------------------------------------------------
#define FQ_PITCH 400
#define FV_PITCH 144
#define F_SQ 0
#define F_SK 25600
#define F_SVH 51200
#define F_SVL 60416
#define FLASH2_SMEM 69632

__global__ __launch_bounds__(128)
void flash_mma_kernel()
{
    extern __shared__ char sm[];
    const uint32_t sb = smem_u32(sm);
    const int tid  = threadIdx.x;
    const int wid  = tid >> 5;
    const int lane = tid & 31;
    const int q0 = blockIdx.x * 64;
    const int bh = blockIdx.y;

    const __nv_bfloat16* Qg  = g_qp   + ((size_t)bh * NSEQ + q0) * KQ;
    const __nv_bfloat16* Kg  = g_kp   + (size_t)bh * NSEQ * KQ;
    const __nv_bfloat16* Vhg = g_vthi + (size_t)bh * DH * NSEQ;
    const __nv_bfloat16* Vlg = g_vtlo + (size_t)bh * DH * NSEQ;

    // Load Q tile: row = tid>>1, 12 quads starting at (tid&1)*12
    {
        const int row = tid >> 1;
        const int qb  = (tid & 1) * 12;
        const uint4* srcq = (const uint4*)(Qg + (size_t)row * KQ) + qb;
        char* dst = sm + F_SQ + row * FQ_PITCH + qb * 16;
        #pragma unroll
        for (int it = 0; it < 12; ++it)
            *(uint4*)(dst + it * 16) = srcq[it];
    }

    // ldmatrix bases
    const uint32_t a_base  = sb + F_SQ + (wid * 16 + (lane & 15)) * FQ_PITCH + (lane >> 4) * 16;
    const uint32_t bK_base = sb + F_SK + ((lane & 7) + ((lane >> 4) << 3)) * FQ_PITCH
                                       + ((lane >> 3) & 1) * 16;
    const uint32_t bV_off  = ((lane & 7) + ((lane >> 4) << 3)) * FV_PITCH + ((lane >> 3) & 1) * 16;
    const uint32_t bVh_base = sb + F_SVH + bV_off;
    const uint32_t bVl_base = sb + F_SVL + bV_off;

    float m0 = -CUDART_INF_F, m1 = -CUDART_INF_F, l0 = 0.0f, l1 = 0.0f;
    float oa[8][4];
    #pragma unroll
    for (int i = 0; i < 8; ++i)
        #pragma unroll
        for (int j = 0; j < 4; ++j) oa[i][j] = 0.0f;

    #pragma unroll 1
    for (int kt = 0; kt < NSEQ / 64; ++kt) {
        __syncthreads();     // all warps done reading previous K/V (and Q stored, 1st iter)
        {   // load K tile
            const int row = tid >> 1;
            const int qb  = (tid & 1) * 12;
            const uint4* srck = (const uint4*)(Kg + (size_t)(kt * 64 + row) * KQ) + qb;
            char* dst = sm + F_SK + row * FQ_PITCH + qb * 16;
            #pragma unroll
            for (int it = 0; it < 12; ++it)
                *(uint4*)(dst + it * 16) = srck[it];
        }
        {   // load V^T hi/lo tiles: rows d, 8 quads of 16B (64 bf16)
            #pragma unroll
            for (int it = 0; it < 4; ++it) {
                const int idx = tid + it * 128;
                const int d = idx >> 3, q = idx & 7;
                const size_t go = (size_t)d * NSEQ + kt * 64 + q * 8;
                *(uint4*)(sm + F_SVH + d * FV_PITCH + q * 16) = *(const uint4*)(Vhg + go);
                *(uint4*)(sm + F_SVL + d * FV_PITCH + q * 16) = *(const uint4*)(Vlg + go);
            }
        }
        __syncthreads();

        // ---- S = Q * K^T over k' = 192 (12 k-steps) ----
        float sa[8][4];
        #pragma unroll
        for (int i = 0; i < 8; ++i)
            #pragma unroll
            for (int j = 0; j < 4; ++j) sa[i][j] = 0.0f;

        #pragma unroll
        for (int ks = 0; ks < 12; ++ks) {
            uint32_t a[4];
            ldsm4(a, a_base + ks * 32);
            #pragma unroll
            for (int nb = 0; nb < 4; ++nb) {
                uint32_t b[4];
                ldsm4(b, bK_base + nb * (16 * FQ_PITCH) + ks * 32);
                hmma(sa[nb * 2],     a, &b[0]);
                hmma(sa[nb * 2 + 1], a, &b[2]);
            }
        }

        // ---- online softmax (rows r0 = wid*16 + lane>>2, r1 = r0+8) ----
        float mx0 = sa[0][0], mx1 = sa[0][2];
        #pragma unroll
        for (int nf = 0; nf < 8; ++nf) {
            mx0 = fmaxf(mx0, fmaxf(sa[nf][0], sa[nf][1]));
            mx1 = fmaxf(mx1, fmaxf(sa[nf][2], sa[nf][3]));
        }
        mx0 = fmaxf(mx0, __shfl_xor_sync(0xffffffffu, mx0, 1));
        mx0 = fmaxf(mx0, __shfl_xor_sync(0xffffffffu, mx0, 2));
        mx1 = fmaxf(mx1, __shfl_xor_sync(0xffffffffu, mx1, 1));
        mx1 = fmaxf(mx1, __shfl_xor_sync(0xffffffffu, mx1, 2));

        const float mn0 = fmaxf(m0, mx0);
        const float mn1 = fmaxf(m1, mx1);
        const float al0 = fast_exp(m0 - mn0);
        const float al1 = fast_exp(m1 - mn1);
        m0 = mn0; m1 = mn1;

        float rs0 = 0.0f, rs1 = 0.0f;
        #pragma unroll
        for (int nf = 0; nf < 8; ++nf) {
            sa[nf][0] = fast_exp(sa[nf][0] - mn0);
            sa[nf][1] = fast_exp(sa[nf][1] - mn0);
            sa[nf][2] = fast_exp(sa[nf][2] - mn1);
            sa[nf][3] = fast_exp(sa[nf][3] - mn1);
            rs0 += sa[nf][0] + sa[nf][1];
            rs1 += sa[nf][2] + sa[nf][3];
        }
        rs0 += __shfl_xor_sync(0xffffffffu, rs0, 1);
        rs0 += __shfl_xor_sync(0xffffffffu, rs0, 2);
        rs1 += __shfl_xor_sync(0xffffffffu, rs1, 1);
        rs1 += __shfl_xor_sync(0xffffffffu, rs1, 2);
        l0 = l0 * al0 + rs0;
        l1 = l1 * al1 + rs1;

        #pragma unroll
        for (int nf = 0; nf < 8; ++nf) {
            oa[nf][0] *= al0; oa[nf][1] *= al0;
            oa[nf][2] *= al1; oa[nf][3] *= al1;
        }

        // ---- O += Phi*Vh + Plo*Vh + Phi*Vl  (4 k-steps of 16 keys) ----
        #pragma unroll
        for (int ks = 0; ks < 4; ++ks) {
            const int f0 = 2 * ks, f1 = 2 * ks + 1;
            uint32_t ah[4], al_[4];
            {
                const float p00 = sa[f0][0], p01 = sa[f0][1];
                const float p02 = sa[f0][2], p03 = sa[f0][3];
                const float p10 = sa[f1][0], p11 = sa[f1][1];
                const float p12 = sa[f1][2], p13 = sa[f1][3];
                ah[0] = pk2(p00, p01);
                ah[1] = pk2(p02, p03);
                ah[2] = pk2(p10, p11);
                ah[3] = pk2(p12, p13);
                al_[0] = pk2(p00 - __bfloat162float(__float2bfloat16(p00)),
                             p01 - __bfloat162float(__float2bfloat16(p01)));
                al_[1] = pk2(p02 - __bfloat162float(__float2bfloat16(p02)),
                             p03 - __bfloat162float(__float2bfloat16(p03)));
                al_[2] = pk2(p10 - __bfloat162float(__float2bfloat16(p10)),
                             p11 - __bfloat162float(__float2bfloat16(p11)));
                al_[3] = pk2(p12 - __bfloat162float(__float2bfloat16(p12)),
                             p13 - __bfloat162float(__float2bfloat16(p13)));
            }
            #pragma unroll
            for (int nb = 0; nb < 4; ++nb) {
                uint32_t bh_[4], bl_[4];
                ldsm4(bh_, bVh_base + nb * (16 * FV_PITCH) + ks * 32);
                hmma(oa[nb * 2],     ah,  &bh_[0]);
                hmma(oa[nb * 2 + 1], ah,  &bh_[2]);
                hmma(oa[nb * 2],     al_, &bh_[0]);
                hmma(oa[nb * 2 + 1], al_, &bh_[2]);
                ldsm4(bl_, bVl_base + nb * (16 * FV_PITCH) + ks * 32);
                hmma(oa[nb * 2],     ah,  &bl_[0]);
                hmma(oa[nb * 2 + 1], ah,  &bl_[2]);
            }
        }
    }

    // ---- writeout: O rows r0/r1, cols d = idx*8 + (lane&3)*2 ----
    const int b = bh >> 4;
    const int h = bh & 15;
    const int r0 = q0 + wid * 16 + (lane >> 2);
    const float i0 = 1.0f / l0;
    const float i1 = 1.0f / l1;
    #pragma unroll
    for (int idx = 0; idx < 8; ++idx) {
        const int d = idx * 8 + (lane & 3) * 2;
        float* p0 = g_o + (size_t)(b * NSEQ + r0) * CDIM + h * DH + d;
        float* p1 = g_o + (size_t)(b * NSEQ + r0 + 8) * CDIM + h * DH + d;
        *(float2*)p0 = make_float2(oa[idx][0] * i0, oa[idx][1] * i0);
        *(float2*)p1 = make_float2(oa[idx][2] * i1, oa[idx][3] * i1);
    }
}

// ---------------------------------------------------------------------------
// Launch
// ---------------------------------------------------------------------------
extern "C" void kernel_launch(void* const* d_in, const int* in_sizes, int n_in,
                              void* d_out, int out_size)
{
    const float* x      = (const float*)d_in[0];
    const float* cosp   = (const float*)d_in[1];
    const float* sinp   = (const float*)d_in[2];
    const float* w_qkv  = (const float*)d_in[3];
    const float* w_proj = (const float*)d_in[4];
    const float* qg     = (const float*)d_in[5];
    const float* kg     = (const float*)d_in[6];
    float* out          = (float*)d_out;
    (void)in_sizes; (void)n_in; (void)out_size;

    cudaFuncSetAttribute(gemm_mma<0>, cudaFuncAttributeMaxDynamicSharedMemorySize, GSMEM);
    cudaFuncSetAttribute(gemm_mma<1>, cudaFuncAttributeMaxDynamicSharedMemorySize, GSMEM);
    cudaFuncSetAttribute(flash_mma_kernel, cudaFuncAttributeMaxDynamicSharedMemorySize, FLASH2_SMEM);

    void *p_go, *p_xp, *p_op, *p_wqp, *p_wpp;
    cudaGetSymbolAddress(&p_go,  g_o);
    cudaGetSymbolAddress(&p_xp,  g_xp);
    cudaGetSymbolAddress(&p_op,  g_op);
    cudaGetSymbolAddress(&p_wqp, g_wqp);
    cudaGetSymbolAddress(&p_wpp, g_wpp);

    // 0) Pack dense-GEMM operands
    pack_a_kernel<<<(MROWS*GK  + 255)/256, 256>>>(x,      (__nv_bfloat16*)p_xp,  MROWS*GK);
    pack_b_kernel<<<(3*CDIM*GK + 255)/256, 256>>>(w_qkv,  (__nv_bfloat16*)p_wqp, 3*CDIM*GK);
    pack_b_kernel<<<(CDIM*GK   + 255)/256, 256>>>(w_proj, (__nv_bfloat16*)p_wpp, CDIM*GK);

    // 1) QKV GEMM -> fp32 g_q/g_k/g_v (B,H,N,D)
    gemm_mma<1><<<dim3(3*CDIM/128, MROWS/128), 256, GSMEM>>>(
        (const __nv_bfloat16*)p_xp, (const __nv_bfloat16*)p_wqp, nullptr, 3*CDIM);

    // 2) RMSNorm + RoPE + pack -> g_qp/g_kp;  V transpose+split -> g_vthi/g_vtlo
    rmsrope_pack_kernel<<<dim3((2*BATCH*HEADS*NSEQ)/16, 2), 256>>>(cosp, sinp, qg, kg);
    vtrans_kernel<<<dim3(NSEQ/64, BATCH*HEADS), 128>>>();

    // 3) Flash attention (HMMA) -> g_o (B,N,C)
    flash_mma_kernel<<<dim3(NSEQ/64, BATCH*HEADS), 128, FLASH2_SMEM>>>();

    // 4) Pack attention output, projection GEMM
    pack_a_kernel<<<(MROWS*GK + 255)/256, 256>>>((const float*)p_go, (__nv_bfloat16*)p_op, MROWS*GK);
    gemm_mma<0><<<dim3(CDIM/128, MROWS/128), 256, GSMEM>>>(
        (const __nv_bfloat16*)p_op, (const __nv_bfloat16*)p_wpp, out, CDIM);
}

// round 9
// speedup vs baseline: 2.1086x; 1.1282x over previous
#include <cuda_runtime.h>
#include <cuda_bf16.h>
#include <math_constants.h>
#include <cstdint>

// Problem constants
#define BATCH 4
#define NSEQ  2048
#define CDIM  1024
#define HEADS 16
#define DH    64
#define MROWS (BATCH*NSEQ)                 // 8192
#define GK    1024                         // logical inner K of dense GEMMs
#define KP    3072                         // packed K (3-term split)
#define KQ    192                          // packed head dim (3-term split)
#define QKV_ELEMS (BATCH*HEADS*NSEQ*DH)    // 8388608

// Scratch (static device globals)
__device__ float g_q[QKV_ELEMS];
__device__ float g_k[QKV_ELEMS];
__device__ float g_v[QKV_ELEMS];
__device__ float g_o[MROWS*CDIM];

__device__ __nv_bfloat16 g_xp [MROWS*KP];
__device__ __nv_bfloat16 g_op [MROWS*KP];
__device__ __nv_bfloat16 g_wqp[3*CDIM*KP];
__device__ __nv_bfloat16 g_wpp[CDIM*KP];

__device__ __nv_bfloat16 g_qp  [BATCH*HEADS*NSEQ*KQ];
__device__ __nv_bfloat16 g_kp  [BATCH*HEADS*NSEQ*KQ];
__device__ __nv_bfloat16 g_vthi[BATCH*HEADS*DH*NSEQ];
__device__ __nv_bfloat16 g_vtlo[BATCH*HEADS*DH*NSEQ];

// ---------------------------------------------------------------------------
// helpers
// ---------------------------------------------------------------------------
__device__ __forceinline__ uint32_t smem_u32(const void* p) {
    uint32_t a;
    asm("{ .reg .u64 t; cvta.to.shared.u64 t, %1; cvt.u32.u64 %0, t; }" : "=r"(a) : "l"(p));
    return a;
}
__device__ __forceinline__ void ldsm4(uint32_t* r, uint32_t addr) {
    asm volatile("ldmatrix.sync.aligned.m8n8.x4.shared.b16 {%0,%1,%2,%3}, [%4];"
                 : "=r"(r[0]), "=r"(r[1]), "=r"(r[2]), "=r"(r[3]) : "r"(addr));
}
__device__ __forceinline__ void hmma(float* d, const uint32_t* a, const uint32_t* b) {
    asm volatile(
        "mma.sync.aligned.m16n8k16.row.col.f32.bf16.bf16.f32 "
        "{%0,%1,%2,%3}, {%4,%5,%6,%7}, {%8,%9}, {%0,%1,%2,%3};"
        : "+f"(d[0]), "+f"(d[1]), "+f"(d[2]), "+f"(d[3])
        : "r"(a[0]), "r"(a[1]), "r"(a[2]), "r"(a[3]), "r"(b[0]), "r"(b[1]));
}
__device__ __forceinline__ uint32_t pk2(float e0, float e1) {
    uint32_t r;
    asm("cvt.rn.bf16x2.f32 %0, %1, %2;" : "=r"(r) : "f"(e1), "f"(e0));
    return r;
}
__device__ __forceinline__ void cpasync16(uint32_t dst, const void* src) {
    asm volatile("cp.async.cg.shared.global [%0], [%1], 16;" :: "r"(dst), "l"(src));
}
#define CP_COMMIT()  asm volatile("cp.async.commit_group;" ::: "memory")
#define CP_WAIT0()   asm volatile("cp.async.wait_group 0;" ::: "memory")
#define CP_WAIT1()   asm volatile("cp.async.wait_group 1;" ::: "memory")

// FFMA-only exp (no MUFU): exp(x) for x <= 0, rel err ~2.4e-6.
__device__ __forceinline__ float fast_exp(float x) {
    float y = x * 1.4426950408889634f;
    y = fmaxf(y, -45.0f);
    const float C = 12582912.0f;
    float z  = y + C;
    int   iz = __float_as_int(z);
    float fi = z - C;
    float f  = y - fi;
    float p  = 1.3333558e-3f;
    p = fmaf(p, f, 9.6181291e-3f);
    p = fmaf(p, f, 5.5504109e-2f);
    p = fmaf(p, f, 2.4022651e-1f);
    p = fmaf(p, f, 6.9314718e-1f);
    p = fmaf(p, f, 1.0f);
    int e = ((iz & 0x7FFFFF) - 0x400000) << 23;
    return __int_as_float(__float_as_int(p) + e);
}

// ---------------------------------------------------------------------------
// Pack kernels: A=[hi|lo|hi], B=[hi|hi|lo], K'=3072.
// ---------------------------------------------------------------------------
__global__ __launch_bounds__(256)
void pack_a_kernel(const float* __restrict__ src, __nv_bfloat16* __restrict__ dst, int nelem)
{
    const int i = blockIdx.x * blockDim.x + threadIdx.x;
    if (i >= nelem) return;
    const int m = i >> 10, k = i & 1023;
    const float v = src[i];
    const __nv_bfloat16 h = __float2bfloat16(v);
    const __nv_bfloat16 l = __float2bfloat16(v - __bfloat162float(h));
    __nv_bfloat16* row = dst + (size_t)m * KP;
    row[k] = h; row[k + 1024] = l; row[k + 2048] = h;
}
__global__ __launch_bounds__(256)
void pack_b_kernel(const float* __restrict__ src, __nv_bfloat16* __restrict__ dst, int nelem)
{
    const int i = blockIdx.x * blockDim.x + threadIdx.x;
    if (i >= nelem) return;
    const int m = i >> 10, k = i & 1023;
    const float v = src[i];
    const __nv_bfloat16 h = __float2bfloat16(v);
    const __nv_bfloat16 l = __float2bfloat16(v - __bfloat162float(h));
    __nv_bfloat16* row = dst + (size_t)m * KP;
    row[k] = h; row[k + 1024] = h; row[k + 2048] = l;
}

// ---------------------------------------------------------------------------
// Dense NT GEMM v2: 128x128 tile, 128 threads, warp tile 64x64 (2x2 warps),
// BK=32, 3-stage cp.async pipeline. hmma/ldsm ratio 4.
// ---------------------------------------------------------------------------
#define GPITCH_B 112                    // bytes per 32-element row (64B data + pad)
#define GTILE_B (128*GPITCH_B)          // 14336 B per operand tile
#define GSTAGE_B (2*GTILE_B)            // 28672 B per stage
#define GSMEM (3*GSTAGE_B)              // 86016 B

template<int EPI>
__global__ __launch_bounds__(128)
void gemm_mma(const __nv_bfloat16* __restrict__ Ap, const __nv_bfloat16* __restrict__ Bp,
              float* __restrict__ C, int Nglob)
{
    extern __shared__ char smem[];
    const uint32_t sbase = smem_u32(smem);

    const int tid  = threadIdx.x;
    const int wid  = tid >> 5;
    const int lane = tid & 31;
    const int wm   = wid & 1;          // m warp coord (x64)
    const int wn   = wid >> 1;         // n warp coord (x64)
    const int m0   = blockIdx.y * 128;
    const int n0   = blockIdx.x * 128;

    // load mapping: 512 quads per operand tile; thread does 4 A + 4 B quads
    const int lrow = tid >> 2;         // 0..31 base rows (x4 iterations)
    const int lq   = tid & 3;          // quad within 64B chunk

    const uint32_t a_off = (uint32_t)((wm*64 + (lane & 15)) * GPITCH_B + (lane >> 4) * 16);
    const uint32_t b_off = (uint32_t)((wn*64 + (lane & 7) + ((lane >> 4) << 3)) * GPITCH_B
                                      + ((lane >> 3) & 1) * 16);

    float acc[4][8][4];
    #pragma unroll
    for (int mi = 0; mi < 4; ++mi)
        #pragma unroll
        for (int nf = 0; nf < 8; ++nf)
            #pragma unroll
            for (int j = 0; j < 4; ++j) acc[mi][nf][j] = 0.0f;

    const int T = KP / 32;             // 96

    auto issue = [&](int t) {
        const uint32_t sA = sbase + (t % 3) * GSTAGE_B;
        const uint32_t sB = sA + GTILE_B;
        const int kc = t * 32;
        #pragma unroll
        for (int i = 0; i < 4; ++i) {
            const int row = lrow + i * 32;
            cpasync16(sA + row * GPITCH_B + lq * 16,
                      Ap + (size_t)(m0 + row) * KP + kc + lq * 8);
        }
        #pragma unroll
        for (int i = 0; i < 4; ++i) {
            const int row = lrow + i * 32;
            cpasync16(sB + row * GPITCH_B + lq * 16,
                      Bp + (size_t)(n0 + row) * KP + kc + lq * 8);
        }
    };

    issue(0); CP_COMMIT();
    issue(1); CP_COMMIT();

    #pragma unroll 1
    for (int t = 0; t < T; ++t) {
        if (t + 1 < T) { CP_WAIT1(); } else { CP_WAIT0(); }
        __syncthreads();
        if (t + 2 < T) { issue(t + 2); CP_COMMIT(); }

        const uint32_t sA = sbase + (t % 3) * GSTAGE_B;
        const uint32_t sB = sA + GTILE_B;
        #pragma unroll
        for (int ks = 0; ks < 2; ++ks) {
            uint32_t a[4][4], b[4][4];
            #pragma unroll
            for (int mi = 0; mi < 4; ++mi)
                ldsm4(a[mi], sA + a_off + mi * (16*GPITCH_B) + ks * 32);
            #pragma unroll
            for (int nb = 0; nb < 4; ++nb)
                ldsm4(b[nb], sB + b_off + nb * (16*GPITCH_B) + ks * 32);
            #pragma unroll
            for (int mi = 0; mi < 4; ++mi)
                #pragma unroll
                for (int nb = 0; nb < 4; ++nb) {
                    hmma(acc[mi][nb*2],   a[mi], &b[nb][0]);
                    hmma(acc[mi][nb*2+1], a[mi], &b[nb][2]);
                }
        }
    }

    const int rbase = m0 + wm * 64 + (lane >> 2);
    const int cbase = n0 + wn * 64 + (lane & 3) * 2;
    #pragma unroll
    for (int mi = 0; mi < 4; ++mi) {
        #pragma unroll
        for (int nf = 0; nf < 8; ++nf) {
            const int r0 = rbase + mi * 16;
            const int c  = cbase + nf * 8;
            const float2 v01 = make_float2(acc[mi][nf][0], acc[mi][nf][1]);
            const float2 v23 = make_float2(acc[mi][nf][2], acc[mi][nf][3]);
            if (EPI == 0) {
                *(float2*)(C + (size_t)r0 * Nglob + c)       = v01;
                *(float2*)(C + (size_t)(r0 + 8) * Nglob + c) = v23;
            } else {
                const int sel = c >> 10;
                const int rem = c & 1023;
                const int h   = rem >> 6;
                const int dcl = rem & 63;
                float* base = (sel == 0) ? g_q : ((sel == 1) ? g_k : g_v);
                {
                    const int m = r0, b = m >> 11, n = m & 2047;
                    *(float2*)(base + (size_t)((b * HEADS + h) * NSEQ + n) * DH + dcl) = v01;
                }
                {
                    const int m = r0 + 8, b = m >> 11, n = m & 2047;
                    *(float2*)(base + (size_t)((b * HEADS + h) * NSEQ + n) * DH + dcl) = v23;
                }
            }
        }
    }
}

// ---------------------------------------------------------------------------
// Fused RMSNorm + RoPE + split-bf16 pack (q scaled by 0.125).
// ---------------------------------------------------------------------------
__global__ __launch_bounds__(256)
void rmsrope_pack_kernel(const float* __restrict__ cosp, const float* __restrict__ sinp,
                         const float* __restrict__ qg, const float* __restrict__ kg)
{
    const int wrow = (blockIdx.x * blockDim.x + threadIdx.x) >> 5;
    const int lane = threadIdx.x & 31;
    const int isq  = (blockIdx.y == 0);
    const float* arr   = isq ? g_q : g_k;
    const float* gamma = isq ? qg  : kg;

    const float* row = arr + (size_t)wrow * DH;
    const int n = wrow & (NSEQ - 1);

    float2 x = *(const float2*)(row + lane * 2);
    float ss = x.x * x.x + x.y * x.y;
    #pragma unroll
    for (int o = 16; o; o >>= 1) ss += __shfl_xor_sync(0xffffffffu, ss, o);
    const float norm = rsqrtf(ss * (1.0f / 64.0f) + 1e-6f);

    const float g0 = gamma[lane * 2], g1 = gamma[lane * 2 + 1];
    const float q0 = x.x * norm * g0;
    const float q1 = x.y * norm * g1;

    const float* cr = cosp + n * DH + lane * 2;
    const float* sr = sinp + n * DH + lane * 2;
    const float scale = isq ? 0.125f : 1.0f;
    const float v0 = (q0 * cr[0] - q1 * sr[0]) * scale;
    const float v1 = (q1 * cr[1] + q0 * sr[1]) * scale;

    const float h0 = __bfloat162float(__float2bfloat16(v0));
    const float h1 = __bfloat162float(__float2bfloat16(v1));
    const uint32_t HP = pk2(v0, v1);
    const uint32_t LP = pk2(v0 - h0, v1 - h1);

    uint32_t* dst = (uint32_t*)((isq ? g_qp : g_kp) + (size_t)wrow * KQ);
    if (isq) { dst[lane] = HP; dst[32 + lane] = LP; dst[64 + lane] = HP; }
    else     { dst[lane] = HP; dst[32 + lane] = HP; dst[64 + lane] = LP; }
}

// ---------------------------------------------------------------------------
// V transpose + split: fp32 g_v (bh,n,d) -> bf16 g_vthi/g_vtlo (bh,d,n).
// ---------------------------------------------------------------------------
__global__ __launch_bounds__(128)
void vtrans_kernel()
{
    __shared__ float s[64 * 68];
    const int tid = threadIdx.x;
    const int n0  = blockIdx.x * 64;
    const int bh  = blockIdx.y;
    const float* src = g_v + ((size_t)bh * NSEQ + n0) * DH;

    #pragma unroll
    for (int it = 0; it < 8; ++it) {
        const int idx = tid + it * 128;
        const int n = idx >> 4, q = (idx & 15) * 4;
        *(float4*)&s[n * 68 + q] = *(const float4*)(src + (size_t)n * DH + q);
    }
    __syncthreads();

    const int d  = tid >> 1;
    const int nh = (tid & 1) * 32;
    uint32_t hibuf[16], lobuf[16];
    #pragma unroll
    for (int j = 0; j < 16; ++j) {
        const float a = s[(nh + 2*j) * 68 + d];
        const float b = s[(nh + 2*j + 1) * 68 + d];
        const float ha = __bfloat162float(__float2bfloat16(a));
        const float hb = __bfloat162float(__float2bfloat16(b));
        hibuf[j] = pk2(a, b);
        lobuf[j] = pk2(a - ha, b - hb);
    }
    uint32_t* dh = (uint32_t*)(g_vthi + ((size_t)bh * DH + d) * NSEQ + n0 + nh);
    uint32_t* dl = (uint32_t*)(g_vtlo + ((size_t)bh * DH + d) * NSEQ + n0 + nh);
    #pragma unroll
    for (int j = 0; j < 16; ++j) { dh[j] = hibuf[j]; dl[j] = lobuf[j]; }
}

// ---------------------------------------------------------------------------
// Flash attention v2 (HMMA): 128 q-rows per block, 8 warps,
// 2-stage cp.async K/V pipeline. Warp w owns q rows 16w..16w+15.
// smem: Q 128x400, K 2x(64x400), V 2x(64x144 hi + 64x144 lo) = 139264 B.
// ---------------------------------------------------------------------------
#define FQ_PITCH 400
#define FV_PITCH 144
#define F_SQ   0
#define F_SK   51200                      // + st*25600
#define F_SV   102400                     // + st*18432 ; lo at +9216
#define FLASH2_SMEM 139264

__global__ __launch_bounds__(256)
void flash_mma_kernel()
{
    extern __shared__ char sm[];
    const uint32_t sb = smem_u32(sm);
    const int tid  = threadIdx.x;
    const int wid  = tid >> 5;
    const int lane = tid & 31;
    const int q0 = blockIdx.x * 128;
    const int bh = blockIdx.y;

    const __nv_bfloat16* Qg  = g_qp   + ((size_t)bh * NSEQ + q0) * KQ;
    const __nv_bfloat16* Kg  = g_kp   + (size_t)bh * NSEQ * KQ;
    const __nv_bfloat16* Vhg = g_vthi + (size_t)bh * DH * NSEQ;
    const __nv_bfloat16* Vlg = g_vtlo + (size_t)bh * DH * NSEQ;

    // Load Q tile: 128 rows x 24 quads = 3072 quads, 12 per thread
    #pragma unroll
    for (int i = 0; i < 12; ++i) {
        const int idx = tid + i * 256;
        const int row = idx / 24, q = idx % 24;
        *(uint4*)(sm + F_SQ + row * FQ_PITCH + q * 16) =
            *(const uint4*)(Qg + (size_t)row * KQ + q * 8);
    }

    auto issue_kv = [&](int kt, int st) {
        const uint32_t sk = sb + F_SK + st * 25600;
        const uint32_t sv = sb + F_SV + st * 18432;
        #pragma unroll
        for (int i = 0; i < 6; ++i) {                    // K: 1536 quads
            const int idx = tid + i * 256;
            const int row = idx / 24, q = idx % 24;
            cpasync16(sk + row * FQ_PITCH + q * 16,
                      Kg + (size_t)(kt * 64 + row) * KQ + q * 8);
        }
        #pragma unroll
        for (int i = 0; i < 2; ++i) {                    // Vhi: 512 quads
            const int idx = tid + i * 256;
            const int d = idx >> 3, q = idx & 7;
            cpasync16(sv + d * FV_PITCH + q * 16,
                      Vhg + (size_t)d * NSEQ + kt * 64 + q * 8);
        }
        #pragma unroll
        for (int i = 0; i < 2; ++i) {                    // Vlo: 512 quads
            const int idx = tid + i * 256;
            const int d = idx >> 3, q = idx & 7;
            cpasync16(sv + 9216 + d * FV_PITCH + q * 16,
                      Vlg + (size_t)d * NSEQ + kt * 64 + q * 8);
        }
    };

    // ldmatrix bases (stage-relative offsets added per iteration)
    const uint32_t a_base = sb + F_SQ + (wid * 16 + (lane & 15)) * FQ_PITCH + (lane >> 4) * 16;
    const uint32_t bK_off = ((lane & 7) + ((lane >> 4) << 3)) * FQ_PITCH + ((lane >> 3) & 1) * 16;
    const uint32_t bV_off = ((lane & 7) + ((lane >> 4) << 3)) * FV_PITCH + ((lane >> 3) & 1) * 16;

    float m0 = -CUDART_INF_F, m1 = -CUDART_INF_F, l0 = 0.0f, l1 = 0.0f;
    float oa[8][4];
    #pragma unroll
    for (int i = 0; i < 8; ++i)
        #pragma unroll
        for (int j = 0; j < 4; ++j) oa[i][j] = 0.0f;

    issue_kv(0, 0); CP_COMMIT();

    #pragma unroll 1
    for (int kt = 0; kt < NSEQ / 64; ++kt) {
        const int st = kt & 1;
        CP_WAIT0();
        __syncthreads();               // stage st ready to all; prev compute on st^1 done
        if (kt + 1 < NSEQ / 64) { issue_kv(kt + 1, st ^ 1); CP_COMMIT(); }

        const uint32_t bK_base  = sb + F_SK + st * 25600 + bK_off;
        const uint32_t bVh_base = sb + F_SV + st * 18432 + bV_off;
        const uint32_t bVl_base = bVh_base + 9216;

        // ---- S = Q * K^T over k' = 192 (12 k-steps) ----
        float sa[8][4];
        #pragma unroll
        for (int i = 0; i < 8; ++i)
            #pragma unroll
            for (int j = 0; j < 4; ++j) sa[i][j] = 0.0f;

        #pragma unroll
        for (int ks = 0; ks < 12; ++ks) {
            uint32_t a[4];
            ldsm4(a, a_base + ks * 32);
            #pragma unroll
            for (int nb = 0; nb < 4; ++nb) {
                uint32_t b[4];
                ldsm4(b, bK_base + nb * (16 * FQ_PITCH) + ks * 32);
                hmma(sa[nb * 2],     a, &b[0]);
                hmma(sa[nb * 2 + 1], a, &b[2]);
            }
        }

        // ---- online softmax ----
        float mx0 = sa[0][0], mx1 = sa[0][2];
        #pragma unroll
        for (int nf = 0; nf < 8; ++nf) {
            mx0 = fmaxf(mx0, fmaxf(sa[nf][0], sa[nf][1]));
            mx1 = fmaxf(mx1, fmaxf(sa[nf][2], sa[nf][3]));
        }
        mx0 = fmaxf(mx0, __shfl_xor_sync(0xffffffffu, mx0, 1));
        mx0 = fmaxf(mx0, __shfl_xor_sync(0xffffffffu, mx0, 2));
        mx1 = fmaxf(mx1, __shfl_xor_sync(0xffffffffu, mx1, 1));
        mx1 = fmaxf(mx1, __shfl_xor_sync(0xffffffffu, mx1, 2));

        const float mn0 = fmaxf(m0, mx0);
        const float mn1 = fmaxf(m1, mx1);
        const float al0 = fast_exp(m0 - mn0);
        const float al1 = fast_exp(m1 - mn1);
        m0 = mn0; m1 = mn1;

        float rs0 = 0.0f, rs1 = 0.0f;
        #pragma unroll
        for (int nf = 0; nf < 8; ++nf) {
            sa[nf][0] = fast_exp(sa[nf][0] - mn0);
            sa[nf][1] = fast_exp(sa[nf][1] - mn0);
            sa[nf][2] = fast_exp(sa[nf][2] - mn1);
            sa[nf][3] = fast_exp(sa[nf][3] - mn1);
            rs0 += sa[nf][0] + sa[nf][1];
            rs1 += sa[nf][2] + sa[nf][3];
        }
        rs0 += __shfl_xor_sync(0xffffffffu, rs0, 1);
        rs0 += __shfl_xor_sync(0xffffffffu, rs0, 2);
        rs1 += __shfl_xor_sync(0xffffffffu, rs1, 1);
        rs1 += __shfl_xor_sync(0xffffffffu, rs1, 2);
        l0 = l0 * al0 + rs0;
        l1 = l1 * al1 + rs1;

        #pragma unroll
        for (int nf = 0; nf < 8; ++nf) {
            oa[nf][0] *= al0; oa[nf][1] *= al0;
            oa[nf][2] *= al1; oa[nf][3] *= al1;
        }

        // ---- O += Phi*Vh + Plo*Vh + Phi*Vl ----
        #pragma unroll
        for (int ks = 0; ks < 4; ++ks) {
            const int f0 = 2 * ks, f1 = 2 * ks + 1;
            uint32_t ah[4], al_[4];
            {
                const float p00 = sa[f0][0], p01 = sa[f0][1];
                const float p02 = sa[f0][2], p03 = sa[f0][3];
                const float p10 = sa[f1][0], p11 = sa[f1][1];
                const float p12 = sa[f1][2], p13 = sa[f1][3];
                ah[0] = pk2(p00, p01);
                ah[1] = pk2(p02, p03);
                ah[2] = pk2(p10, p11);
                ah[3] = pk2(p12, p13);
                al_[0] = pk2(p00 - __bfloat162float(__float2bfloat16(p00)),
                             p01 - __bfloat162float(__float2bfloat16(p01)));
                al_[1] = pk2(p02 - __bfloat162float(__float2bfloat16(p02)),
                             p03 - __bfloat162float(__float2bfloat16(p03)));
                al_[2] = pk2(p10 - __bfloat162float(__float2bfloat16(p10)),
                             p11 - __bfloat162float(__float2bfloat16(p11)));
                al_[3] = pk2(p12 - __bfloat162float(__float2bfloat16(p12)),
                             p13 - __bfloat162float(__float2bfloat16(p13)));
            }
            #pragma unroll
            for (int nb = 0; nb < 4; ++nb) {
                uint32_t bh_[4], bl_[4];
                ldsm4(bh_, bVh_base + nb * (16 * FV_PITCH) + ks * 32);
                hmma(oa[nb * 2],     ah,  &bh_[0]);
                hmma(oa[nb * 2 + 1], ah,  &bh_[2]);
                hmma(oa[nb * 2],     al_, &bh_[0]);
                hmma(oa[nb * 2 + 1], al_, &bh_[2]);
                ldsm4(bl_, bVl_base + nb * (16 * FV_PITCH) + ks * 32);
                hmma(oa[nb * 2],     ah,  &bl_[0]);
                hmma(oa[nb * 2 + 1], ah,  &bl_[2]);
            }
        }
    }

    // ---- writeout ----
    const int b = bh >> 4;
    const int h = bh & 15;
    const int r0 = q0 + wid * 16 + (lane >> 2);
    const float i0 = 1.0f / l0;
    const float i1 = 1.0f / l1;
    #pragma unroll
    for (int idx = 0; idx < 8; ++idx) {
        const int d = idx * 8 + (lane & 3) * 2;
        float* p0 = g_o + (size_t)(b * NSEQ + r0) * CDIM + h * DH + d;
        float* p1 = g_o + (size_t)(b * NSEQ + r0 + 8) * CDIM + h * DH + d;
        *(float2*)p0 = make_float2(oa[idx][0] * i0, oa[idx][1] * i0);
        *(float2*)p1 = make_float2(oa[idx][2] * i1, oa[idx][3] * i1);
    }
}

// ---------------------------------------------------------------------------
// Launch
// ---------------------------------------------------------------------------
extern "C" void kernel_launch(void* const* d_in, const int* in_sizes, int n_in,
                              void* d_out, int out_size)
{
    const float* x      = (const float*)d_in[0];
    const float* cosp   = (const float*)d_in[1];
    const float* sinp   = (const float*)d_in[2];
    const float* w_qkv  = (const float*)d_in[3];
    const float* w_proj = (const float*)d_in[4];
    const float* qg     = (const float*)d_in[5];
    const float* kg     = (const float*)d_in[6];
    float* out          = (float*)d_out;
    (void)in_sizes; (void)n_in; (void)out_size;

    cudaFuncSetAttribute(gemm_mma<0>, cudaFuncAttributeMaxDynamicSharedMemorySize, GSMEM);
    cudaFuncSetAttribute(gemm_mma<1>, cudaFuncAttributeMaxDynamicSharedMemorySize, GSMEM);
    cudaFuncSetAttribute(flash_mma_kernel, cudaFuncAttributeMaxDynamicSharedMemorySize, FLASH2_SMEM);

    void *p_go, *p_xp, *p_op, *p_wqp, *p_wpp;
    cudaGetSymbolAddress(&p_go,  g_o);
    cudaGetSymbolAddress(&p_xp,  g_xp);
    cudaGetSymbolAddress(&p_op,  g_op);
    cudaGetSymbolAddress(&p_wqp, g_wqp);
    cudaGetSymbolAddress(&p_wpp, g_wpp);

    // 0) Pack dense-GEMM operands
    pack_a_kernel<<<(MROWS*GK  + 255)/256, 256>>>(x,      (__nv_bfloat16*)p_xp,  MROWS*GK);
    pack_b_kernel<<<(3*CDIM*GK + 255)/256, 256>>>(w_qkv,  (__nv_bfloat16*)p_wqp, 3*CDIM*GK);
    pack_b_kernel<<<(CDIM*GK   + 255)/256, 256>>>(w_proj, (__nv_bfloat16*)p_wpp, CDIM*GK);

    // 1) QKV GEMM -> fp32 g_q/g_k/g_v (B,H,N,D)
    gemm_mma<1><<<dim3(3*CDIM/128, MROWS/128), 128, GSMEM>>>(
        (const __nv_bfloat16*)p_xp, (const __nv_bfloat16*)p_wqp, nullptr, 3*CDIM);

    // 2) RMSNorm + RoPE + pack;  V transpose + split
    rmsrope_pack_kernel<<<dim3((2*BATCH*HEADS*NSEQ)/16, 2), 256>>>(cosp, sinp, qg, kg);
    vtrans_kernel<<<dim3(NSEQ/64, BATCH*HEADS), 128>>>();

    // 3) Flash attention (HMMA, 128-q blocks, cp.async pipeline) -> g_o (B,N,C)
    flash_mma_kernel<<<dim3(NSEQ/128, BATCH*HEADS), 256, FLASH2_SMEM>>>();

    // 4) Pack attention output, projection GEMM
    pack_a_kernel<<<(MROWS*GK + 255)/256, 256>>>((const float*)p_go, (__nv_bfloat16*)p_op, MROWS*GK);
    gemm_mma<0><<<dim3(CDIM/128, MROWS/128), 128, GSMEM>>>(
        (const __nv_bfloat16*)p_op, (const __nv_bfloat16*)p_wpp, out, CDIM);
}

// round 12
// speedup vs baseline: 2.4502x; 1.1620x over previous
#include <cuda_runtime.h>
#include <cuda_bf16.h>
#include <math_constants.h>
#include <cstdint>

// Problem constants
#define BATCH 4
#define NSEQ  2048
#define CDIM  1024
#define HEADS 16
#define DH    64
#define MROWS (BATCH*NSEQ)                 // 8192
#define GK    1024
#define KP    3072                         // packed K (3-term split)
#define KQ    192                          // packed head dim (3-term split)
#define QKV_ELEMS (BATCH*HEADS*NSEQ*DH)

// Scratch
__device__ float g_q[QKV_ELEMS];
__device__ float g_k[QKV_ELEMS];
__device__ float g_v[QKV_ELEMS];
__device__ float g_o[MROWS*CDIM];

__device__ __nv_bfloat16 g_xp [MROWS*KP];
__device__ __nv_bfloat16 g_op [MROWS*KP];
__device__ __nv_bfloat16 g_wqp[3*CDIM*KP];
__device__ __nv_bfloat16 g_wpp[CDIM*KP];

__device__ __nv_bfloat16 g_qp  [BATCH*HEADS*NSEQ*KQ];
__device__ __nv_bfloat16 g_kp  [BATCH*HEADS*NSEQ*KQ];
__device__ __nv_bfloat16 g_vthi[BATCH*HEADS*DH*NSEQ];
__device__ __nv_bfloat16 g_vtlo[BATCH*HEADS*DH*NSEQ];

// ---------------------------------------------------------------------------
// helpers
// ---------------------------------------------------------------------------
__device__ __forceinline__ uint32_t smem_u32(const void* p) {
    uint32_t a;
    asm("{ .reg .u64 t; cvta.to.shared.u64 t, %1; cvt.u32.u64 %0, t; }" : "=r"(a) : "l"(p));
    return a;
}
__device__ __forceinline__ void ldsm4(uint32_t* r, uint32_t addr) {
    asm volatile("ldmatrix.sync.aligned.m8n8.x4.shared.b16 {%0,%1,%2,%3}, [%4];"
                 : "=r"(r[0]), "=r"(r[1]), "=r"(r[2]), "=r"(r[3]) : "r"(addr));
}
__device__ __forceinline__ void hmma(float* d, const uint32_t* a, const uint32_t* b) {
    asm volatile(
        "mma.sync.aligned.m16n8k16.row.col.f32.bf16.bf16.f32 "
        "{%0,%1,%2,%3}, {%4,%5,%6,%7}, {%8,%9}, {%0,%1,%2,%3};"
        : "+f"(d[0]), "+f"(d[1]), "+f"(d[2]), "+f"(d[3])
        : "r"(a[0]), "r"(a[1]), "r"(a[2]), "r"(a[3]), "r"(b[0]), "r"(b[1]));
}
__device__ __forceinline__ uint32_t pk2(float e0, float e1) {
    uint32_t r;
    asm("cvt.rn.bf16x2.f32 %0, %1, %2;" : "=r"(r) : "f"(e1), "f"(e0));
    return r;
}
__device__ __forceinline__ float tobf(float v) {
    return __bfloat162float(__float2bfloat16(v));
}
__device__ __forceinline__ void cpasync16(uint32_t dst, const void* src) {
    asm volatile("cp.async.cg.shared.global [%0], [%1], 16;" :: "r"(dst), "l"(src));
}
#define CP_COMMIT()  asm volatile("cp.async.commit_group;" ::: "memory")
#define CP_WAIT0()   asm volatile("cp.async.wait_group 0;" ::: "memory")
#define CP_WAIT1()   asm volatile("cp.async.wait_group 1;" ::: "memory")

// FFMA-only exp (no MUFU): exp(x) for x <= 0, rel err ~2.4e-6.
__device__ __forceinline__ float fast_exp(float x) {
    float y = x * 1.4426950408889634f;
    y = fmaxf(y, -45.0f);
    const float C = 12582912.0f;
    float z  = y + C;
    int   iz = __float_as_int(z);
    float fi = z - C;
    float f  = y - fi;
    float p  = 1.3333558e-3f;
    p = fmaf(p, f, 9.6181291e-3f);
    p = fmaf(p, f, 5.5504109e-2f);
    p = fmaf(p, f, 2.4022651e-1f);
    p = fmaf(p, f, 6.9314718e-1f);
    p = fmaf(p, f, 1.0f);
    int e = ((iz & 0x7FFFFF) - 0x400000) << 23;
    return __int_as_float(__float_as_int(p) + e);
}

// ---------------------------------------------------------------------------
// Pack kernels (vectorized): A=[hi|lo|hi], B=[hi|hi|lo], K'=3072.
// ---------------------------------------------------------------------------
__global__ __launch_bounds__(256)
void pack_a_kernel(const float* __restrict__ src, __nv_bfloat16* __restrict__ dst, int nquads)
{
    const int i = blockIdx.x * blockDim.x + threadIdx.x;
    if (i >= nquads) return;
    const int i4 = i * 4;
    const int m = i4 >> 10, k = i4 & 1023;
    const float4 v = *(const float4*)(src + i4);
    const uint32_t h01 = pk2(v.x, v.y), h23 = pk2(v.z, v.w);
    const uint32_t l01 = pk2(v.x - tobf(v.x), v.y - tobf(v.y));
    const uint32_t l23 = pk2(v.z - tobf(v.z), v.w - tobf(v.w));
    __nv_bfloat16* row = dst + (size_t)m * KP;
    *(uint2*)(row + k)        = make_uint2(h01, h23);
    *(uint2*)(row + k + 1024) = make_uint2(l01, l23);
    *(uint2*)(row + k + 2048) = make_uint2(h01, h23);
}
__global__ __launch_bounds__(256)
void pack_b_kernel(const float* __restrict__ src, __nv_bfloat16* __restrict__ dst, int nquads)
{
    const int i = blockIdx.x * blockDim.x + threadIdx.x;
    if (i >= nquads) return;
    const int i4 = i * 4;
    const int m = i4 >> 10, k = i4 & 1023;
    const float4 v = *(const float4*)(src + i4);
    const uint32_t h01 = pk2(v.x, v.y), h23 = pk2(v.z, v.w);
    const uint32_t l01 = pk2(v.x - tobf(v.x), v.y - tobf(v.y));
    const uint32_t l23 = pk2(v.z - tobf(v.z), v.w - tobf(v.w));
    __nv_bfloat16* row = dst + (size_t)m * KP;
    *(uint2*)(row + k)        = make_uint2(h01, h23);
    *(uint2*)(row + k + 1024) = make_uint2(h01, h23);
    *(uint2*)(row + k + 2048) = make_uint2(l01, l23);
}

// ---------------------------------------------------------------------------
// Dense NT GEMM v3: 128x128 tile, 128 threads, warp tile 64x64 (2x2 warps),
// BK=64, 3-stage cp.async pipeline. Row pitch 144B -> conflict-free ldsm.
// ---------------------------------------------------------------------------
#define GPITCH_B 144
#define GTILE_B (128*GPITCH_B)          // 18432 B per operand tile
#define GSTAGE_B (2*GTILE_B)            // 36864 B per stage
#define GSMEM (3*GSTAGE_B)              // 110592 B

template<int EPI>
__global__ __launch_bounds__(128)
void gemm_mma(const __nv_bfloat16* __restrict__ Ap, const __nv_bfloat16* __restrict__ Bp,
              float* __restrict__ C, int Nglob)
{
    extern __shared__ char smem[];
    const uint32_t sbase = smem_u32(smem);

    const int tid  = threadIdx.x;
    const int wid  = tid >> 5;
    const int lane = tid & 31;
    const int wm   = wid & 1;
    const int wn   = wid >> 1;
    const int m0   = blockIdx.y * 128;
    const int n0   = blockIdx.x * 128;

    const int lrow = tid >> 3;         // 0..15 (x8 row-groups of 16)
    const int lq   = tid & 7;          // quad within 128B row

    const uint32_t a_off = (uint32_t)((wm*64 + (lane & 15)) * GPITCH_B + (lane >> 4) * 16);
    const uint32_t b_off = (uint32_t)((wn*64 + (lane & 7) + ((lane >> 4) << 3)) * GPITCH_B
                                      + ((lane >> 3) & 1) * 16);

    float acc[4][8][4];
    #pragma unroll
    for (int mi = 0; mi < 4; ++mi)
        #pragma unroll
        for (int nf = 0; nf < 8; ++nf)
            #pragma unroll
            for (int j = 0; j < 4; ++j) acc[mi][nf][j] = 0.0f;

    const int T = KP / 64;             // 48

    auto issue = [&](int t) {
        const uint32_t sA = sbase + (t % 3) * GSTAGE_B;
        const uint32_t sB = sA + GTILE_B;
        const int kc = t * 64;
        #pragma unroll
        for (int i = 0; i < 8; ++i) {
            const int row = lrow + i * 16;
            cpasync16(sA + row * GPITCH_B + lq * 16,
                      Ap + (size_t)(m0 + row) * KP + kc + lq * 8);
        }
        #pragma unroll
        for (int i = 0; i < 8; ++i) {
            const int row = lrow + i * 16;
            cpasync16(sB + row * GPITCH_B + lq * 16,
                      Bp + (size_t)(n0 + row) * KP + kc + lq * 8);
        }
    };

    issue(0); CP_COMMIT();
    issue(1); CP_COMMIT();

    #pragma unroll 1
    for (int t = 0; t < T; ++t) {
        if (t + 1 < T) { CP_WAIT1(); } else { CP_WAIT0(); }
        __syncthreads();
        if (t + 2 < T) { issue(t + 2); CP_COMMIT(); }

        const uint32_t sA = sbase + (t % 3) * GSTAGE_B;
        const uint32_t sB = sA + GTILE_B;
        #pragma unroll
        for (int ks = 0; ks < 4; ++ks) {
            uint32_t a[4][4], b[4][4];
            #pragma unroll
            for (int mi = 0; mi < 4; ++mi)
                ldsm4(a[mi], sA + a_off + mi * (16*GPITCH_B) + ks * 32);
            #pragma unroll
            for (int nb = 0; nb < 4; ++nb)
                ldsm4(b[nb], sB + b_off + nb * (16*GPITCH_B) + ks * 32);
            #pragma unroll
            for (int mi = 0; mi < 4; ++mi)
                #pragma unroll
                for (int nb = 0; nb < 4; ++nb) {
                    hmma(acc[mi][nb*2],   a[mi], &b[nb][0]);
                    hmma(acc[mi][nb*2+1], a[mi], &b[nb][2]);
                }
        }
    }

    const int rbase = m0 + wm * 64 + (lane >> 2);
    const int cbase = n0 + wn * 64 + (lane & 3) * 2;
    #pragma unroll
    for (int mi = 0; mi < 4; ++mi) {
        #pragma unroll
        for (int nf = 0; nf < 8; ++nf) {
            const int r0 = rbase + mi * 16;
            const int c  = cbase + nf * 8;
            const float2 v01 = make_float2(acc[mi][nf][0], acc[mi][nf][1]);
            const float2 v23 = make_float2(acc[mi][nf][2], acc[mi][nf][3]);
            if (EPI == 0) {
                *(float2*)(C + (size_t)r0 * Nglob + c)       = v01;
                *(float2*)(C + (size_t)(r0 + 8) * Nglob + c) = v23;
            } else {
                const int sel = c >> 10;
                const int rem = c & 1023;
                const int h   = rem >> 6;
                const int dcl = rem & 63;
                float* base = (sel == 0) ? g_q : ((sel == 1) ? g_k : g_v);
                {
                    const int m = r0, b = m >> 11, n = m & 2047;
                    *(float2*)(base + (size_t)((b * HEADS + h) * NSEQ + n) * DH + dcl) = v01;
                }
                {
                    const int m = r0 + 8, b = m >> 11, n = m & 2047;
                    *(float2*)(base + (size_t)((b * HEADS + h) * NSEQ + n) * DH + dcl) = v23;
                }
            }
        }
    }
}

// ---------------------------------------------------------------------------
// Fused RMSNorm + RoPE + split-bf16 pack (q scaled by 0.125).
// ---------------------------------------------------------------------------
__global__ __launch_bounds__(256)
void rmsrope_pack_kernel(const float* __restrict__ cosp, const float* __restrict__ sinp,
                         const float* __restrict__ qg, const float* __restrict__ kg)
{
    const int wrow = (blockIdx.x * blockDim.x + threadIdx.x) >> 5;
    const int lane = threadIdx.x & 31;
    const int isq  = (blockIdx.y == 0);
    const float* arr   = isq ? g_q : g_k;
    const float* gamma = isq ? qg  : kg;

    const float* row = arr + (size_t)wrow * DH;
    const int n = wrow & (NSEQ - 1);

    float2 x = *(const float2*)(row + lane * 2);
    float ss = x.x * x.x + x.y * x.y;
    #pragma unroll
    for (int o = 16; o; o >>= 1) ss += __shfl_xor_sync(0xffffffffu, ss, o);
    const float norm = rsqrtf(ss * (1.0f / 64.0f) + 1e-6f);

    const float g0 = gamma[lane * 2], g1 = gamma[lane * 2 + 1];
    const float q0 = x.x * norm * g0;
    const float q1 = x.y * norm * g1;

    const float* cr = cosp + n * DH + lane * 2;
    const float* sr = sinp + n * DH + lane * 2;
    const float scale = isq ? 0.125f : 1.0f;
    const float v0 = (q0 * cr[0] - q1 * sr[0]) * scale;
    const float v1 = (q1 * cr[1] + q0 * sr[1]) * scale;

    const uint32_t HP = pk2(v0, v1);
    const uint32_t LP = pk2(v0 - tobf(v0), v1 - tobf(v1));

    uint32_t* dst = (uint32_t*)((isq ? g_qp : g_kp) + (size_t)wrow * KQ);
    if (isq) { dst[lane] = HP; dst[32 + lane] = LP; dst[64 + lane] = HP; }
    else     { dst[lane] = HP; dst[32 + lane] = HP; dst[64 + lane] = LP; }
}

// ---------------------------------------------------------------------------
// V transpose + split: fp32 g_v (bh,n,d) -> bf16 g_vthi/g_vtlo (bh,d,n).
// ---------------------------------------------------------------------------
__global__ __launch_bounds__(128)
void vtrans_kernel()
{
    __shared__ float s[64 * 68];
    const int tid = threadIdx.x;
    const int n0  = blockIdx.x * 64;
    const int bh  = blockIdx.y;
    const float* src = g_v + ((size_t)bh * NSEQ + n0) * DH;

    #pragma unroll
    for (int it = 0; it < 8; ++it) {
        const int idx = tid + it * 128;
        const int n = idx >> 4, q = (idx & 15) * 4;
        *(float4*)&s[n * 68 + q] = *(const float4*)(src + (size_t)n * DH + q);
    }
    __syncthreads();

    const int d  = tid >> 1;
    const int nh = (tid & 1) * 32;
    uint32_t hibuf[16], lobuf[16];
    #pragma unroll
    for (int j = 0; j < 16; ++j) {
        const float a = s[(nh + 2*j) * 68 + d];
        const float b = s[(nh + 2*j + 1) * 68 + d];
        hibuf[j] = pk2(a, b);
        lobuf[j] = pk2(a - tobf(a), b - tobf(b));
    }
    uint32_t* dh = (uint32_t*)(g_vthi + ((size_t)bh * DH + d) * NSEQ + n0 + nh);
    uint32_t* dl = (uint32_t*)(g_vtlo + ((size_t)bh * DH + d) * NSEQ + n0 + nh);
    #pragma unroll
    for (int j = 0; j < 16; ++j) { dh[j] = hibuf[j]; dl[j] = lobuf[j]; }
}

// ---------------------------------------------------------------------------
// Flash attention v3 (HMMA): 256 q-rows per block, 8 warps; warp owns 32 q
// rows (two m16 tiles sharing K/V fragments). 2-stage cp.async K/V pipeline.
// smem: Q 256x400 = 102400, K 2x25600, V 2x(9216 hi + 9216 lo) = 190464 B.
// ---------------------------------------------------------------------------
#define FQ_PITCH 400
#define FV_PITCH 144
#define F_SQ   0
#define F_SK   102400                     // + st*25600
#define F_SV   153600                     // + st*18432 ; lo at +9216
#define FLASH2_SMEM 190464

__global__ __launch_bounds__(256)
void flash_mma_kernel()
{
    extern __shared__ char sm[];
    const uint32_t sb = smem_u32(sm);
    const int tid  = threadIdx.x;
    const int wid  = tid >> 5;
    const int lane = tid & 31;
    const int q0 = blockIdx.x * 256;
    const int bh = blockIdx.y;

    const __nv_bfloat16* Qg  = g_qp   + ((size_t)bh * NSEQ + q0) * KQ;
    const __nv_bfloat16* Kg  = g_kp   + (size_t)bh * NSEQ * KQ;
    const __nv_bfloat16* Vhg = g_vthi + (size_t)bh * DH * NSEQ;
    const __nv_bfloat16* Vlg = g_vtlo + (size_t)bh * DH * NSEQ;

    auto issue_kv = [&](int kt, int st) {
        const uint32_t sk = sb + F_SK + st * 25600;
        const uint32_t sv = sb + F_SV + st * 18432;
        #pragma unroll
        for (int i = 0; i < 6; ++i) {                    // K: 1536 quads
            const int idx = tid + i * 256;
            const int row = idx / 24, q = idx % 24;
            cpasync16(sk + row * FQ_PITCH + q * 16,
                      Kg + (size_t)(kt * 64 + row) * KQ + q * 8);
        }
        #pragma unroll
        for (int i = 0; i < 2; ++i) {                    // Vhi: 512 quads
            const int idx = tid + i * 256;
            const int d = idx >> 3, q = idx & 7;
            cpasync16(sv + d * FV_PITCH + q * 16,
                      Vhg + (size_t)d * NSEQ + kt * 64 + q * 8);
        }
        #pragma unroll
        for (int i = 0; i < 2; ++i) {                    // Vlo: 512 quads
            const int idx = tid + i * 256;
            const int d = idx >> 3, q = idx & 7;
            cpasync16(sv + 9216 + d * FV_PITCH + q * 16,
                      Vlg + (size_t)d * NSEQ + kt * 64 + q * 8);
        }
    };

    issue_kv(0, 0); CP_COMMIT();

    // Load Q tile: 256 rows x 24 quads = 6144 quads, 24 per thread
    #pragma unroll
    for (int i = 0; i < 24; ++i) {
        const int idx = tid + i * 256;
        const int row = idx / 24, q = idx % 24;
        *(uint4*)(sm + F_SQ + row * FQ_PITCH + q * 16) =
            *(const uint4*)(Qg + (size_t)row * KQ + q * 8);
    }

    // ldmatrix bases
    uint32_t a_base[2];
    #pragma unroll
    for (int mt = 0; mt < 2; ++mt)
        a_base[mt] = sb + F_SQ + (wid * 32 + mt * 16 + (lane & 15)) * FQ_PITCH
                     + (lane >> 4) * 16;
    const uint32_t bK_off = ((lane & 7) + ((lane >> 4) << 3)) * FQ_PITCH + ((lane >> 3) & 1) * 16;
    const uint32_t bV_off = ((lane & 7) + ((lane >> 4) << 3)) * FV_PITCH + ((lane >> 3) & 1) * 16;

    float m_[2][2], l_[2][2];
    float oa[2][8][4];
    #pragma unroll
    for (int mt = 0; mt < 2; ++mt) {
        m_[mt][0] = -CUDART_INF_F; m_[mt][1] = -CUDART_INF_F;
        l_[mt][0] = 0.0f; l_[mt][1] = 0.0f;
        #pragma unroll
        for (int i = 0; i < 8; ++i)
            #pragma unroll
            for (int j = 0; j < 4; ++j) oa[mt][i][j] = 0.0f;
    }

    #pragma unroll 1
    for (int kt = 0; kt < NSEQ / 64; ++kt) {
        const int st = kt & 1;
        CP_WAIT0();
        __syncthreads();
        if (kt + 1 < NSEQ / 64) { issue_kv(kt + 1, st ^ 1); CP_COMMIT(); }

        const uint32_t bK_base  = sb + F_SK + st * 25600 + bK_off;
        const uint32_t bVh_base = sb + F_SV + st * 18432 + bV_off;
        const uint32_t bVl_base = bVh_base + 9216;

        // ---- S = Q * K^T over k' = 192 (12 k-steps); K frags shared by both mt ----
        float sa[2][8][4];
        #pragma unroll
        for (int mt = 0; mt < 2; ++mt)
            #pragma unroll
            for (int i = 0; i < 8; ++i)
                #pragma unroll
                for (int j = 0; j < 4; ++j) sa[mt][i][j] = 0.0f;

        #pragma unroll
        for (int ks = 0; ks < 12; ++ks) {
            uint32_t b[4][4];
            #pragma unroll
            for (int nb = 0; nb < 4; ++nb)
                ldsm4(b[nb], bK_base + nb * (16 * FQ_PITCH) + ks * 32);
            #pragma unroll
            for (int mt = 0; mt < 2; ++mt) {
                uint32_t a[4];
                ldsm4(a, a_base[mt] + ks * 32);
                #pragma unroll
                for (int nb = 0; nb < 4; ++nb) {
                    hmma(sa[mt][nb * 2],     a, &b[nb][0]);
                    hmma(sa[mt][nb * 2 + 1], a, &b[nb][2]);
                }
            }
        }

        // ---- online softmax per mt ----
        #pragma unroll
        for (int mt = 0; mt < 2; ++mt) {
            float mx0 = sa[mt][0][0], mx1 = sa[mt][0][2];
            #pragma unroll
            for (int nf = 0; nf < 8; ++nf) {
                mx0 = fmaxf(mx0, fmaxf(sa[mt][nf][0], sa[mt][nf][1]));
                mx1 = fmaxf(mx1, fmaxf(sa[mt][nf][2], sa[mt][nf][3]));
            }
            mx0 = fmaxf(mx0, __shfl_xor_sync(0xffffffffu, mx0, 1));
            mx0 = fmaxf(mx0, __shfl_xor_sync(0xffffffffu, mx0, 2));
            mx1 = fmaxf(mx1, __shfl_xor_sync(0xffffffffu, mx1, 1));
            mx1 = fmaxf(mx1, __shfl_xor_sync(0xffffffffu, mx1, 2));

            const float mn0 = fmaxf(m_[mt][0], mx0);
            const float mn1 = fmaxf(m_[mt][1], mx1);
            const float al0 = fast_exp(m_[mt][0] - mn0);
            const float al1 = fast_exp(m_[mt][1] - mn1);
            m_[mt][0] = mn0; m_[mt][1] = mn1;

            float rs0 = 0.0f, rs1 = 0.0f;
            #pragma unroll
            for (int nf = 0; nf < 8; ++nf) {
                sa[mt][nf][0] = fast_exp(sa[mt][nf][0] - mn0);
                sa[mt][nf][1] = fast_exp(sa[mt][nf][1] - mn0);
                sa[mt][nf][2] = fast_exp(sa[mt][nf][2] - mn1);
                sa[mt][nf][3] = fast_exp(sa[mt][nf][3] - mn1);
                rs0 += sa[mt][nf][0] + sa[mt][nf][1];
                rs1 += sa[mt][nf][2] + sa[mt][nf][3];
            }
            rs0 += __shfl_xor_sync(0xffffffffu, rs0, 1);
            rs0 += __shfl_xor_sync(0xffffffffu, rs0, 2);
            rs1 += __shfl_xor_sync(0xffffffffu, rs1, 1);
            rs1 += __shfl_xor_sync(0xffffffffu, rs1, 2);
            l_[mt][0] = l_[mt][0] * al0 + rs0;
            l_[mt][1] = l_[mt][1] * al1 + rs1;

            #pragma unroll
            for (int nf = 0; nf < 8; ++nf) {
                oa[mt][nf][0] *= al0; oa[mt][nf][1] *= al0;
                oa[mt][nf][2] *= al1; oa[mt][nf][3] *= al1;
            }
        }

        // ---- O += Phi*Vh + Plo*Vh + Phi*Vl; V frags shared by both mt ----
        #pragma unroll
        for (int ks = 0; ks < 4; ++ks) {
            uint32_t ah[2][4], al[2][4];
            #pragma unroll
            for (int mt = 0; mt < 2; ++mt) {
                const int f0 = 2 * ks, f1 = 2 * ks + 1;
                const float p00 = sa[mt][f0][0], p01 = sa[mt][f0][1];
                const float p02 = sa[mt][f0][2], p03 = sa[mt][f0][3];
                const float p10 = sa[mt][f1][0], p11 = sa[mt][f1][1];
                const float p12 = sa[mt][f1][2], p13 = sa[mt][f1][3];
                ah[mt][0] = pk2(p00, p01);
                ah[mt][1] = pk2(p02, p03);
                ah[mt][2] = pk2(p10, p11);
                ah[mt][3] = pk2(p12, p13);
                al[mt][0] = pk2(p00 - tobf(p00), p01 - tobf(p01));
                al[mt][1] = pk2(p02 - tobf(p02), p03 - tobf(p03));
                al[mt][2] = pk2(p10 - tobf(p10), p11 - tobf(p11));
                al[mt][3] = pk2(p12 - tobf(p12), p13 - tobf(p13));
            }
            #pragma unroll
            for (int nb = 0; nb < 4; ++nb) {
                uint32_t bh_[4], bl_[4];
                ldsm4(bh_, bVh_base + nb * (16 * FV_PITCH) + ks * 32);
                #pragma unroll
                for (int mt = 0; mt < 2; ++mt) {
                    hmma(oa[mt][nb * 2],     ah[mt], &bh_[0]);
                    hmma(oa[mt][nb * 2 + 1], ah[mt], &bh_[2]);
                    hmma(oa[mt][nb * 2],     al[mt], &bh_[0]);
                    hmma(oa[mt][nb * 2 + 1], al[mt], &bh_[2]);
                }
                ldsm4(bl_, bVl_base + nb * (16 * FV_PITCH) + ks * 32);
                #pragma unroll
                for (int mt = 0; mt < 2; ++mt) {
                    hmma(oa[mt][nb * 2],     ah[mt], &bl_[0]);
                    hmma(oa[mt][nb * 2 + 1], ah[mt], &bl_[2]);
                }
            }
        }
    }

    // ---- writeout ----
    const int b = bh >> 4;
    const int h = bh & 15;
    #pragma unroll
    for (int mt = 0; mt < 2; ++mt) {
        const int r0 = q0 + wid * 32 + mt * 16 + (lane >> 2);
        const float i0 = 1.0f / l_[mt][0];
        const float i1 = 1.0f / l_[mt][1];
        #pragma unroll
        for (int idx = 0; idx < 8; ++idx) {
            const int d = idx * 8 + (lane & 3) * 2;
            float* p0 = g_o + (size_t)(b * NSEQ + r0) * CDIM + h * DH + d;
            float* p1 = g_o + (size_t)(b * NSEQ + r0 + 8) * CDIM + h * DH + d;
            *(float2*)p0 = make_float2(oa[mt][idx][0] * i0, oa[mt][idx][1] * i0);
            *(float2*)p1 = make_float2(oa[mt][idx][2] * i1, oa[mt][idx][3] * i1);
        }
    }
}

// ---------------------------------------------------------------------------
// Launch
// ---------------------------------------------------------------------------
extern "C" void kernel_launch(void* const* d_in, const int* in_sizes, int n_in,
                              void* d_out, int out_size)
{
    const float* x      = (const float*)d_in[0];
    const float* cosp   = (const float*)d_in[1];
    const float* sinp   = (const float*)d_in[2];
    const float* w_qkv  = (const float*)d_in[3];
    const float* w_proj = (const float*)d_in[4];
    const float* qg     = (const float*)d_in[5];
    const float* kg     = (const float*)d_in[6];
    float* out          = (float*)d_out;
    (void)in_sizes; (void)n_in; (void)out_size;

    cudaFuncSetAttribute(gemm_mma<0>, cudaFuncAttributeMaxDynamicSharedMemorySize, GSMEM);
    cudaFuncSetAttribute(gemm_mma<1>, cudaFuncAttributeMaxDynamicSharedMemorySize, GSMEM);
    cudaFuncSetAttribute(flash_mma_kernel, cudaFuncAttributeMaxDynamicSharedMemorySize, FLASH2_SMEM);

    void *p_go, *p_xp, *p_op, *p_wqp, *p_wpp;
    cudaGetSymbolAddress(&p_go,  g_o);
    cudaGetSymbolAddress(&p_xp,  g_xp);
    cudaGetSymbolAddress(&p_op,  g_op);
    cudaGetSymbolAddress(&p_wqp, g_wqp);
    cudaGetSymbolAddress(&p_wpp, g_wpp);

    // 0) Pack dense-GEMM operands (vectorized: 4 elems/thread)
    pack_a_kernel<<<(MROWS*GK/4  + 255)/256, 256>>>(x,      (__nv_bfloat16*)p_xp,  MROWS*GK/4);
    pack_b_kernel<<<(3*CDIM*GK/4 + 255)/256, 256>>>(w_qkv,  (__nv_bfloat16*)p_wqp, 3*CDIM*GK/4);
    pack_b_kernel<<<(CDIM*GK/4   + 255)/256, 256>>>(w_proj, (__nv_bfloat16*)p_wpp, CDIM*GK/4);

    // 1) QKV GEMM -> fp32 g_q/g_k/g_v (B,H,N,D)
    gemm_mma<1><<<dim3(3*CDIM/128, MROWS/128), 128, GSMEM>>>(
        (const __nv_bfloat16*)p_xp, (const __nv_bfloat16*)p_wqp, nullptr, 3*CDIM);

    // 2) RMSNorm + RoPE + pack;  V transpose + split
    rmsrope_pack_kernel<<<dim3((2*BATCH*HEADS*NSEQ)/16, 2), 256>>>(cosp, sinp, qg, kg);
    vtrans_kernel<<<dim3(NSEQ/64, BATCH*HEADS), 128>>>();

    // 3) Flash attention (HMMA, 256-q blocks, 32 q-rows/warp) -> g_o (B,N,C)
    flash_mma_kernel<<<dim3(NSEQ/256, BATCH*HEADS), 256, FLASH2_SMEM>>>();

    // 4) Pack attention output, projection GEMM
    pack_a_kernel<<<(MROWS*GK/4 + 255)/256, 256>>>((const float*)p_go, (__nv_bfloat16*)p_op, MROWS*GK/4);
    gemm_mma<0><<<dim3(CDIM/128, MROWS/128), 128, GSMEM>>>(
        (const __nv_bfloat16*)p_op, (const __nv_bfloat16*)p_wpp, out, CDIM);
}